// round 1
// baseline (speedup 1.0000x reference)
#include <cuda_runtime.h>
#include <cuda_bf16.h>

// Problem constants
#define BATCH 16
#define NPTS  4096
#define MPTS  1024
#define C1    256
#define C2    512
#define CF    768          // C1 + C2
#define CO    256
#define RTOT  65536        // BATCH * NPTS

// ---------------- scratch (static __device__ globals; no allocation) ----------
__device__ float  g_feat [(size_t)RTOT * CF];   // feat for GEMM1; reused as y2 output of GEMM2
__device__ float  g_y1   [(size_t)RTOT * CO];
__device__ float  g_feat2[(size_t)RTOT * CO];
__device__ float  g_w3   [RTOT * 3];
__device__ int    g_idx3 [RTOT * 3];
__device__ float  g_Bt1  [CF * CO];
__device__ float  g_Bt2  [CO * CO];
__device__ double g_stats[1024];                // [0..511] stage1 (sum,sumsq), [512..1023] stage2
__device__ float  g_scale[512];                 // [0..255] stage1, [256..511] stage2
__device__ float  g_shift[512];

// ---------------- small utility kernels ---------------------------------------
__global__ void zero_stats_kernel(double* stats) {
    stats[threadIdx.x] = 0.0;
}

// W: (N x K) row-major  ->  Bt: (K x N) row-major
__global__ void transpose_w_kernel(const float* __restrict__ W, float* __restrict__ Bt,
                                   int N, int K) {
    __shared__ float t[32][33];
    int k  = blockIdx.x * 32 + threadIdx.x;
    int nn = blockIdx.y * 32 + threadIdx.y;
    if (nn < N && k < K) t[threadIdx.y][threadIdx.x] = W[(size_t)nn * K + k];
    __syncthreads();
    int k2 = blockIdx.x * 32 + threadIdx.y;
    int n2 = blockIdx.y * 32 + threadIdx.x;
    if (k2 < K && n2 < N) Bt[(size_t)k2 * N + n2] = t[threadIdx.x][threadIdx.y];
}

// ---------------- 3-NN + interpolation weights --------------------------------
__global__ void three_nn_kernel(const float* __restrict__ xyz1,
                                const float* __restrict__ xyz2,
                                int* __restrict__ idx_out,
                                float* __restrict__ w_out) {
    __shared__ float sx[MPTS], sy[MPTS], sz[MPTS];
    int b = blockIdx.y;
    const float* p2 = xyz2 + (size_t)b * MPTS * 3;
    for (int i = threadIdx.x; i < MPTS; i += blockDim.x) {
        sx[i] = p2[i * 3 + 0];
        sy[i] = p2[i * 3 + 1];
        sz[i] = p2[i * 3 + 2];
    }
    __syncthreads();

    int n = blockIdx.x * blockDim.x + threadIdx.x;
    size_t r = (size_t)b * NPTS + n;
    float x = xyz1[r * 3 + 0], y = xyz1[r * 3 + 1], z = xyz1[r * 3 + 2];

    float d0 = 1e30f, d1 = 1e30f, d2v = 1e30f;
    int   i0 = 0, i1 = 0, i2 = 0;
    #pragma unroll 4
    for (int j = 0; j < MPTS; j++) {
        float dx = x - sx[j], dy = y - sy[j], dz = z - sz[j];
        float d = dx * dx + dy * dy + dz * dz;
        if (d < d0)        { d2v = d1; i2 = i1; d1 = d0; i1 = i0; d0 = d; i0 = j; }
        else if (d < d1)   { d2v = d1; i2 = i1; d1 = d;  i1 = j; }
        else if (d < d2v)  { d2v = d;  i2 = j; }
    }
    // Hardtanh(0, 1e-10) on squared dists, then inverse-distance weights
    float c0 = fminf(fmaxf(d0, 0.f), 1e-10f);
    float c1 = fminf(fmaxf(d1, 0.f), 1e-10f);
    float c2 = fminf(fmaxf(d2v, 0.f), 1e-10f);
    float v0 = 1.f / c0, v1 = 1.f / c1, v2 = 1.f / c2;
    float s = v0 + v1 + v2;
    w_out[r * 3 + 0] = v0 / s;
    w_out[r * 3 + 1] = v1 / s;
    w_out[r * 3 + 2] = v2 / s;
    idx_out[r * 3 + 0] = i0;
    idx_out[r * 3 + 1] = i1;
    idx_out[r * 3 + 2] = i2;
}

// ---------------- build feat = [interp(512) | points1(256)] -------------------
__global__ void build_feat_kernel(const float* __restrict__ points1,
                                  const float* __restrict__ points2,
                                  const int* __restrict__ idx,
                                  const float* __restrict__ w,
                                  float* __restrict__ feat) {
    int n = blockIdx.x, b = blockIdx.y;
    size_t r = (size_t)b * NPTS + n;
    int i0 = idx[r * 3 + 0], i1 = idx[r * 3 + 1], i2 = idx[r * 3 + 2];
    float w0 = w[r * 3 + 0], w1 = w[r * 3 + 1], w2 = w[r * 3 + 2];
    const float* p0 = points2 + ((size_t)b * MPTS + i0) * C2;
    const float* p1 = points2 + ((size_t)b * MPTS + i1) * C2;
    const float* p2 = points2 + ((size_t)b * MPTS + i2) * C2;
    float* f = feat + r * CF;
    #pragma unroll
    for (int c = threadIdx.x; c < C2; c += 256)
        f[c] = w0 * p0[c] + w1 * p1[c] + w2 * p2[c];
    const float* q = points1 + r * C1;
    f[C2 + threadIdx.x] = q[threadIdx.x];
}

// ---------------- fp32 tiled GEMM: C(MxN) = A(MxK) * B(KxN) + bias ------------
#define BM 128
#define BN 64
#define BK 16

__global__ __launch_bounds__(256)
void gemm_bias_kernel(const float* __restrict__ A, const float* __restrict__ B,
                      const float* __restrict__ bias, float* __restrict__ C,
                      int K, int N) {
    __shared__ float As[BK][BM];
    __shared__ float Bs[BK][BN];
    int tid = threadIdx.x;
    int tx = tid & 15;      // column group (0..15) -> 4 cols each
    int ty = tid >> 4;      // row group    (0..15) -> 8 rows each
    size_t rowBase = (size_t)blockIdx.y * BM;
    int colBase = blockIdx.x * BN;

    const float* Ab = A + rowBase * K;
    const float* Bb = B + colBase;

    int arow = tid >> 2;          // 0..63
    int akq  = tid & 3;           // float4 slot within row
    int brow = tid >> 4;          // 0..15
    int bcol = (tid & 15) * 4;

    float acc[8][4] = {};

    for (int k0 = 0; k0 < K; k0 += BK) {
        #pragma unroll
        for (int it = 0; it < 2; it++) {
            int r = arow + it * 64;
            float4 v = *(const float4*)(Ab + (size_t)r * K + k0 + akq * 4);
            As[akq * 4 + 0][r] = v.x;
            As[akq * 4 + 1][r] = v.y;
            As[akq * 4 + 2][r] = v.z;
            As[akq * 4 + 3][r] = v.w;
        }
        {
            float4 v = *(const float4*)(Bb + (size_t)(k0 + brow) * N + bcol);
            *(float4*)&Bs[brow][bcol] = v;
        }
        __syncthreads();
        #pragma unroll
        for (int k = 0; k < BK; k++) {
            float4 a0 = *(const float4*)&As[k][ty * 8];
            float4 a1 = *(const float4*)&As[k][ty * 8 + 4];
            float4 bv = *(const float4*)&Bs[k][tx * 4];
            float a[8] = {a0.x, a0.y, a0.z, a0.w, a1.x, a1.y, a1.z, a1.w};
            float bb[4] = {bv.x, bv.y, bv.z, bv.w};
            #pragma unroll
            for (int i = 0; i < 8; i++)
                #pragma unroll
                for (int j = 0; j < 4; j++)
                    acc[i][j] += a[i] * bb[j];
        }
        __syncthreads();
    }

    float4 bv = *(const float4*)(bias + colBase + tx * 4);
    #pragma unroll
    for (int i = 0; i < 8; i++) {
        size_t r = rowBase + ty * 8 + i;
        float4 o;
        o.x = acc[i][0] + bv.x;
        o.y = acc[i][1] + bv.y;
        o.z = acc[i][2] + bv.z;
        o.w = acc[i][3] + bv.w;
        *(float4*)(C + r * N + colBase + tx * 4) = o;
    }
}

// ---------------- BN statistics: per-channel sum & sumsq (double atomics) -----
__global__ void stats_kernel(const float* __restrict__ y, double* __restrict__ sums) {
    int c = threadIdx.x;                 // channel 0..255
    const float* p = y + (size_t)blockIdx.x * 256 * CO + c;
    double s = 0.0, s2 = 0.0;
    #pragma unroll 4
    for (int i = 0; i < 256; i++) {
        float v = p[(size_t)i * CO];
        s += v;
        s2 += (double)v * v;
    }
    atomicAdd(&sums[c], s);
    atomicAdd(&sums[CO + c], s2);
}

__global__ void finalize_kernel(const double* __restrict__ sums,
                                const float* __restrict__ g, const float* __restrict__ beta,
                                float* __restrict__ scale, float* __restrict__ shift) {
    int c = threadIdx.x;
    double mean = sums[c] * (1.0 / RTOT);
    double var = sums[CO + c] * (1.0 / RTOT) - mean * mean;
    float sc = g[c] * rsqrtf((float)var + 1e-5f);
    scale[c] = sc;
    shift[c] = beta[c] - (float)mean * sc;
}

// ---------------- BN apply + ReLU (vectorized) ---------------------------------
__global__ void bn_relu_kernel(const float4* __restrict__ y,
                               const float* __restrict__ scale, const float* __restrict__ shift,
                               float4* __restrict__ out) {
    size_t i = (size_t)blockIdx.x * 256 + threadIdx.x;
    float4 v = y[i];
    int c0 = (int)(i & 63) * 4;
    v.x = fmaxf(v.x * scale[c0 + 0] + shift[c0 + 0], 0.f);
    v.y = fmaxf(v.y * scale[c0 + 1] + shift[c0 + 1], 0.f);
    v.z = fmaxf(v.z * scale[c0 + 2] + shift[c0 + 2], 0.f);
    v.w = fmaxf(v.w * scale[c0 + 3] + shift[c0 + 3], 0.f);
    out[i] = v;
}

// ---------------- final BN + ReLU + transpose to (b, c, n) ---------------------
__global__ void bn_relu_tr_kernel(const float* __restrict__ y,
                                  const float* __restrict__ scale, const float* __restrict__ shift,
                                  float* __restrict__ out) {
    __shared__ float t[32][33];
    int b = blockIdx.z;
    int n0 = blockIdx.x * 32, c0 = blockIdx.y * 32;
    int n = n0 + threadIdx.y, c = c0 + threadIdx.x;
    float v = y[((size_t)b * NPTS + n) * CO + c];
    v = fmaxf(v * scale[c] + shift[c], 0.f);
    t[threadIdx.y][threadIdx.x] = v;
    __syncthreads();
    out[((size_t)b * CO + c0 + threadIdx.y) * NPTS + n0 + threadIdx.x] = t[threadIdx.x][threadIdx.y];
}

// ---------------- launch ---------------------------------------------------------
extern "C" void kernel_launch(void* const* d_in, const int* in_sizes, int n_in,
                              void* d_out, int out_size) {
    const float* xyz1    = (const float*)d_in[0];
    const float* xyz2    = (const float*)d_in[1];
    const float* points1 = (const float*)d_in[2];
    const float* points2 = (const float*)d_in[3];
    const float* W1      = (const float*)d_in[4];
    const float* b1      = (const float*)d_in[5];
    const float* g1      = (const float*)d_in[6];
    const float* beta1   = (const float*)d_in[7];
    const float* W2      = (const float*)d_in[8];
    const float* b2      = (const float*)d_in[9];
    const float* g2      = (const float*)d_in[10];
    const float* beta2   = (const float*)d_in[11];
    float* out = (float*)d_out;

    float *feat, *y1, *feat2, *w3, *Bt1, *Bt2, *scale, *shift;
    int* idx3;
    double* stats;
    cudaGetSymbolAddress((void**)&feat,  g_feat);
    cudaGetSymbolAddress((void**)&y1,    g_y1);
    cudaGetSymbolAddress((void**)&feat2, g_feat2);
    cudaGetSymbolAddress((void**)&w3,    g_w3);
    cudaGetSymbolAddress((void**)&idx3,  g_idx3);
    cudaGetSymbolAddress((void**)&Bt1,   g_Bt1);
    cudaGetSymbolAddress((void**)&Bt2,   g_Bt2);
    cudaGetSymbolAddress((void**)&stats, g_stats);
    cudaGetSymbolAddress((void**)&scale, g_scale);
    cudaGetSymbolAddress((void**)&shift, g_shift);

    zero_stats_kernel<<<1, 1024>>>(stats);
    transpose_w_kernel<<<dim3(CF / 32, CO / 32), dim3(32, 32)>>>(W1, Bt1, CO, CF);
    transpose_w_kernel<<<dim3(CO / 32, CO / 32), dim3(32, 32)>>>(W2, Bt2, CO, CO);

    three_nn_kernel<<<dim3(NPTS / 256, BATCH), 256>>>(xyz1, xyz2, idx3, w3);
    build_feat_kernel<<<dim3(NPTS, BATCH), 256>>>(points1, points2, idx3, w3, feat);

    // layer 1: GEMM(768->256) + BN + ReLU
    gemm_bias_kernel<<<dim3(CO / BN, RTOT / BM), 256>>>(feat, Bt1, b1, y1, CF, CO);
    stats_kernel<<<256, 256>>>(y1, stats);
    finalize_kernel<<<1, 256>>>(stats, g1, beta1, scale, shift);
    bn_relu_kernel<<<(RTOT * CO / 4) / 256, 256>>>((const float4*)y1, scale, shift, (float4*)feat2);

    // layer 2: GEMM(256->256) + BN + ReLU + transpose (y2 reuses g_feat)
    gemm_bias_kernel<<<dim3(CO / BN, RTOT / BM), 256>>>(feat2, Bt2, b2, feat, CO, CO);
    stats_kernel<<<256, 256>>>(feat, stats + 512);
    finalize_kernel<<<1, 256>>>(stats + 512, g2, beta2, scale + 256, shift + 256);
    bn_relu_tr_kernel<<<dim3(NPTS / 32, CO / 32, BATCH), dim3(32, 32)>>>(feat, scale + 256, shift + 256, out);
}

// round 3
// speedup vs baseline: 1.5065x; 1.5065x over previous
#include <cuda_runtime.h>
#include <cuda_bf16.h>
#include <cstdint>

// Problem constants
#define BATCH 16
#define NPTS  4096
#define MPTS  1024
#define C1    256
#define C2    512
#define CF    768
#define CO    256
#define RTOT  65536

// ---------------- scratch (static __device__ globals; no allocation) ----------
__device__ float  g_feat[(size_t)RTOT * CF];   // fp32 feat for GEMM1
__device__ float  g_y   [(size_t)RTOT * CO];   // GEMM output (both layers)
__device__ float  g_a2  [(size_t)RTOT * CO];   // relu(bn(y1)) fp32 input to GEMM2
__device__ unsigned short g_Bhi1[CO * CF];
__device__ unsigned short g_Blo1[CO * CF];
__device__ unsigned short g_Bhi2[CO * CO];
__device__ unsigned short g_Blo2[CO * CO];
__device__ float  g_w3  [RTOT * 3];
__device__ int    g_idx3[RTOT * 3];
__device__ double g_stats[1024];
__device__ float  g_scale[512];
__device__ float  g_shift[512];

// ---------------- helpers ---------------------------------------------------------
__device__ __forceinline__ uint32_t smem_u32(const void* p) {
    uint32_t a;
    asm("{ .reg .u64 t; cvta.to.shared.u64 t, %1; cvt.u32.u64 %0, t; }" : "=r"(a) : "l"(p));
    return a;
}

#define LDSM4(r, addr) \
    asm volatile("ldmatrix.sync.aligned.m8n8.x4.shared.b16 {%0,%1,%2,%3}, [%4];" \
                 : "=r"((r)[0]), "=r"((r)[1]), "=r"((r)[2]), "=r"((r)[3]) : "r"(addr))

#define MMA16816(d, a, b0, b1) \
    asm volatile("mma.sync.aligned.m16n8k16.row.col.f32.bf16.bf16.f32 " \
                 "{%0,%1,%2,%3}, {%4,%5,%6,%7}, {%8,%9}, {%0,%1,%2,%3};" \
                 : "+f"((d)[0]), "+f"((d)[1]), "+f"((d)[2]), "+f"((d)[3]) \
                 : "r"((a)[0]), "r"((a)[1]), "r"((a)[2]), "r"((a)[3]), "r"(b0), "r"(b1))

__device__ __forceinline__ void split4(float4 v, uint2& hi, uint2& lo) {
    __nv_bfloat16 h0 = __float2bfloat16_rn(v.x);
    __nv_bfloat16 h1 = __float2bfloat16_rn(v.y);
    __nv_bfloat16 h2 = __float2bfloat16_rn(v.z);
    __nv_bfloat16 h3 = __float2bfloat16_rn(v.w);
    __nv_bfloat16 l0 = __float2bfloat16_rn(v.x - __bfloat162float(h0));
    __nv_bfloat16 l1 = __float2bfloat16_rn(v.y - __bfloat162float(h1));
    __nv_bfloat16 l2 = __float2bfloat16_rn(v.z - __bfloat162float(h2));
    __nv_bfloat16 l3 = __float2bfloat16_rn(v.w - __bfloat162float(h3));
    hi.x = (uint32_t)__bfloat16_as_ushort(h0) | ((uint32_t)__bfloat16_as_ushort(h1) << 16);
    hi.y = (uint32_t)__bfloat16_as_ushort(h2) | ((uint32_t)__bfloat16_as_ushort(h3) << 16);
    lo.x = (uint32_t)__bfloat16_as_ushort(l0) | ((uint32_t)__bfloat16_as_ushort(l1) << 16);
    lo.y = (uint32_t)__bfloat16_as_ushort(l2) | ((uint32_t)__bfloat16_as_ushort(l3) << 16);
}

// ---------------- small utility kernels -----------------------------------------
__global__ void zero_stats_kernel(double* stats) { stats[threadIdx.x] = 0.0; }

// W (CO x K fp32) -> Bhi/Blo (CO x K bf16)
__global__ void prep_w_kernel(const float* __restrict__ W,
                              unsigned short* __restrict__ Bhi,
                              unsigned short* __restrict__ Blo, int total) {
    int idx = blockIdx.x * 256 + threadIdx.x;
    if (idx >= total) return;
    float v = W[idx];
    __nv_bfloat16 hi = __float2bfloat16_rn(v);
    __nv_bfloat16 lo = __float2bfloat16_rn(v - __bfloat162float(hi));
    Bhi[idx] = __bfloat16_as_ushort(hi);
    Blo[idx] = __bfloat16_as_ushort(lo);
}

// ---------------- 3-NN + interpolation weights ----------------------------------
__global__ void three_nn_kernel(const float* __restrict__ xyz1,
                                const float* __restrict__ xyz2,
                                int* __restrict__ idx_out,
                                float* __restrict__ w_out) {
    __shared__ float sx[MPTS], sy[MPTS], sz[MPTS];
    int b = blockIdx.y;
    const float* p2 = xyz2 + (size_t)b * MPTS * 3;
    for (int i = threadIdx.x; i < MPTS; i += blockDim.x) {
        sx[i] = p2[i * 3 + 0];
        sy[i] = p2[i * 3 + 1];
        sz[i] = p2[i * 3 + 2];
    }
    __syncthreads();

    int n = blockIdx.x * blockDim.x + threadIdx.x;
    size_t r = (size_t)b * NPTS + n;
    float x = xyz1[r * 3 + 0], y = xyz1[r * 3 + 1], z = xyz1[r * 3 + 2];

    float d0 = 1e30f, d1 = 1e30f, d2v = 1e30f;
    int   i0 = 0, i1 = 0, i2 = 0;
    #pragma unroll 4
    for (int j = 0; j < MPTS; j++) {
        float dx = x - sx[j], dy = y - sy[j], dz = z - sz[j];
        float d = dx * dx + dy * dy + dz * dz;
        if (d < d0)        { d2v = d1; i2 = i1; d1 = d0; i1 = i0; d0 = d; i0 = j; }
        else if (d < d1)   { d2v = d1; i2 = i1; d1 = d;  i1 = j; }
        else if (d < d2v)  { d2v = d;  i2 = j; }
    }
    float c0 = fminf(fmaxf(d0, 0.f), 1e-10f);
    float c1 = fminf(fmaxf(d1, 0.f), 1e-10f);
    float c2 = fminf(fmaxf(d2v, 0.f), 1e-10f);
    float v0 = 1.f / c0, v1 = 1.f / c1, v2 = 1.f / c2;
    float s = v0 + v1 + v2;
    w_out[r * 3 + 0] = v0 / s;
    w_out[r * 3 + 1] = v1 / s;
    w_out[r * 3 + 2] = v2 / s;
    idx_out[r * 3 + 0] = i0;
    idx_out[r * 3 + 1] = i1;
    idx_out[r * 3 + 2] = i2;
}

// ---------------- build feat = [interp(512) | points1(256)] (fp32) --------------
__global__ void build_feat_kernel(const float* __restrict__ points1,
                                  const float* __restrict__ points2,
                                  const int* __restrict__ idx,
                                  const float* __restrict__ w,
                                  float* __restrict__ feat) {
    int n = blockIdx.x, b = blockIdx.y;
    size_t r = (size_t)b * NPTS + n;
    int i0 = idx[r * 3 + 0], i1 = idx[r * 3 + 1], i2 = idx[r * 3 + 2];
    float w0 = w[r * 3 + 0], w1 = w[r * 3 + 1], w2 = w[r * 3 + 2];
    const float* p0 = points2 + ((size_t)b * MPTS + i0) * C2;
    const float* p1 = points2 + ((size_t)b * MPTS + i1) * C2;
    const float* p2 = points2 + ((size_t)b * MPTS + i2) * C2;
    float* f = feat + r * CF;
    #pragma unroll
    for (int c = threadIdx.x; c < C2; c += 256)
        f[c] = w0 * p0[c] + w1 * p1[c] + w2 * p2[c];
    f[C2 + threadIdx.x] = points1[r * C1 + threadIdx.x];
}

// ---------------- split-bf16 HMMA GEMM: Y(M x 256) = A(M x K) * B(256 x K)^T ----
// CTA tile 128M x 128N, 512 threads (16 warps, 4M x 4N, warp tile 32x32).
// K-chunk = 32 fp32; A converted to (hi, lo) bf16 in-kernel.
#define BKC 32
#define RS  40    // smem row stride in bf16 (32 + 8 pad) -> 80B, conflict-free ldmatrix

__global__ void __launch_bounds__(512)
mma_gemm_kernel(const float* __restrict__ A,
                const unsigned short* __restrict__ Bhi,
                const unsigned short* __restrict__ Blo,
                float* __restrict__ Y, int K) {
    __shared__ __align__(16) unsigned short As_hi[128 * RS];
    __shared__ __align__(16) unsigned short As_lo[128 * RS];
    __shared__ __align__(16) unsigned short Bs_hi[128 * RS];
    __shared__ __align__(16) unsigned short Bs_lo[128 * RS];

    int tid = threadIdx.x, lane = tid & 31, wid = tid >> 5;
    int wm = wid & 3, wn = wid >> 2;           // warp coords: 4M x 4N

    const float* Ab = A + (size_t)(blockIdx.y * 128) * K;
    const unsigned short* Bhb = Bhi + (size_t)(blockIdx.x * 128) * K;
    const unsigned short* Blb = Blo + (size_t)(blockIdx.x * 128) * K;

    // A slots: 1024 float4 per chunk; thread handles slot tid and tid+512.
    int rA0 = tid >> 3, qA0 = tid & 7;
    int rA1 = (tid + 512) >> 3, qA1 = tid & 7;  // (tid+512)&7 == tid&7
    // B slots: 512 uint4 per chunk per matrix.
    int rB = tid >> 2, qB = tid & 3;

    float4 apf0, apf1;
    uint4 bhpf, blpf;

    auto ldg_chunk = [&](int c) {
        const float* Ac = Ab + c * BKC;
        apf0 = *(const float4*)(Ac + (size_t)rA0 * K + qA0 * 4);
        apf1 = *(const float4*)(Ac + (size_t)rA1 * K + qA1 * 4);
        bhpf = *(const uint4*)(Bhb + (size_t)rB * K + c * BKC + qB * 8);
        blpf = *(const uint4*)(Blb + (size_t)rB * K + c * BKC + qB * 8);
    };

    uint32_t sAhi = smem_u32(As_hi), sAlo = smem_u32(As_lo);
    uint32_t sBhi = smem_u32(Bs_hi), sBlo = smem_u32(Bs_lo);

    float acc[2][4][4] = {};

    int KCH = K / BKC;
    ldg_chunk(0);

    for (int c = 0; c < KCH; c++) {
        // stage prefetched chunk into smem (convert A)
        {
            uint2 hi, lo;
            split4(apf0, hi, lo);
            *(uint2*)&As_hi[rA0 * RS + qA0 * 4] = hi;
            *(uint2*)&As_lo[rA0 * RS + qA0 * 4] = lo;
            split4(apf1, hi, lo);
            *(uint2*)&As_hi[rA1 * RS + qA1 * 4] = hi;
            *(uint2*)&As_lo[rA1 * RS + qA1 * 4] = lo;
            *(uint4*)&Bs_hi[rB * RS + qB * 8] = bhpf;
            *(uint4*)&Bs_lo[rB * RS + qB * 8] = blpf;
        }
        __syncthreads();
        if (c + 1 < KCH) ldg_chunk(c + 1);

        #pragma unroll
        for (int ks = 0; ks < 2; ks++) {
            uint32_t ah[2][4], al[2][4], bh[2][4], bl[2][4];
            int arow = wm * 32 + (lane & 15);
            int akoff = ks * 16 + (lane >> 4) * 8;
            LDSM4(ah[0], sAhi + (uint32_t)((arow) * RS + akoff) * 2);
            LDSM4(ah[1], sAhi + (uint32_t)((arow + 16) * RS + akoff) * 2);
            LDSM4(al[0], sAlo + (uint32_t)((arow) * RS + akoff) * 2);
            LDSM4(al[1], sAlo + (uint32_t)((arow + 16) * RS + akoff) * 2);
            int brow = wn * 32 + (lane & 7) + ((lane >> 4) & 1) * 8;
            int bkoff = ks * 16 + ((lane >> 3) & 1) * 8;
            LDSM4(bh[0], sBhi + (uint32_t)((brow) * RS + bkoff) * 2);
            LDSM4(bh[1], sBhi + (uint32_t)((brow + 16) * RS + bkoff) * 2);
            LDSM4(bl[0], sBlo + (uint32_t)((brow) * RS + bkoff) * 2);
            LDSM4(bl[1], sBlo + (uint32_t)((brow + 16) * RS + bkoff) * 2);

            #pragma unroll
            for (int mi = 0; mi < 2; mi++) {
                #pragma unroll
                for (int nb = 0; nb < 2; nb++) {
                    // frag pair: regs (0,1) -> n block lo8, (2,3) -> n block hi8
                    MMA16816(acc[mi][nb * 2 + 0], ah[mi], bh[nb][0], bh[nb][1]);
                    MMA16816(acc[mi][nb * 2 + 1], ah[mi], bh[nb][2], bh[nb][3]);
                    MMA16816(acc[mi][nb * 2 + 0], ah[mi], bl[nb][0], bl[nb][1]);
                    MMA16816(acc[mi][nb * 2 + 1], ah[mi], bl[nb][2], bl[nb][3]);
                    MMA16816(acc[mi][nb * 2 + 0], al[mi], bh[nb][0], bh[nb][1]);
                    MMA16816(acc[mi][nb * 2 + 1], al[mi], bh[nb][2], bh[nb][3]);
                }
            }
        }
        __syncthreads();
    }

    // epilogue: write fp32
    int ybase_r = blockIdx.y * 128 + wm * 32 + (lane >> 2);
    int ybase_c = blockIdx.x * 128 + wn * 32 + (lane & 3) * 2;
    #pragma unroll
    for (int mi = 0; mi < 2; mi++) {
        #pragma unroll
        for (int ni = 0; ni < 4; ni++) {
            int r = ybase_r + mi * 16;
            int cc = ybase_c + (ni >> 1) * 16 + (ni & 1) * 8;
            float2 v0 = make_float2(acc[mi][ni][0], acc[mi][ni][1]);
            float2 v1 = make_float2(acc[mi][ni][2], acc[mi][ni][3]);
            *(float2*)(Y + (size_t)r * CO + cc) = v0;
            *(float2*)(Y + (size_t)(r + 8) * CO + cc) = v1;
        }
    }
}

// ---------------- BN statistics ---------------------------------------------------
__global__ void stats_kernel(const float* __restrict__ y, double* __restrict__ sums) {
    int c = threadIdx.x;
    const float* p = y + (size_t)blockIdx.x * 256 * CO + c;
    double s = 0.0, s2 = 0.0;
    #pragma unroll 4
    for (int i = 0; i < 256; i++) {
        float v = p[(size_t)i * CO];
        s += v;
        s2 += (double)v * v;
    }
    atomicAdd(&sums[c], s);
    atomicAdd(&sums[CO + c], s2);
}

__global__ void finalize_kernel(const double* __restrict__ sums,
                                const float* __restrict__ g, const float* __restrict__ beta,
                                float* __restrict__ scale, float* __restrict__ shift) {
    int c = threadIdx.x;
    double mean = sums[c] * (1.0 / RTOT);
    double var = sums[CO + c] * (1.0 / RTOT) - mean * mean;
    float sc = g[c] * rsqrtf((float)var + 1e-5f);
    scale[c] = sc;
    shift[c] = beta[c] - (float)mean * sc;
}

// ---------------- BN + ReLU (fp32 out) ---------------------------------------------
__global__ void bn_relu_kernel(const float4* __restrict__ y,
                               const float* __restrict__ scale, const float* __restrict__ shift,
                               float4* __restrict__ out) {
    size_t i = (size_t)blockIdx.x * 256 + threadIdx.x;
    float4 v = y[i];
    int c0 = (int)(i & 63) * 4;
    v.x = fmaxf(v.x * scale[c0 + 0] + shift[c0 + 0], 0.f);
    v.y = fmaxf(v.y * scale[c0 + 1] + shift[c0 + 1], 0.f);
    v.z = fmaxf(v.z * scale[c0 + 2] + shift[c0 + 2], 0.f);
    v.w = fmaxf(v.w * scale[c0 + 3] + shift[c0 + 3], 0.f);
    out[i] = v;
}

// ---------------- final BN + ReLU + transpose to (b, c, n) -------------------------
__global__ void bn_relu_tr_kernel(const float* __restrict__ y,
                                  const float* __restrict__ scale, const float* __restrict__ shift,
                                  float* __restrict__ out) {
    __shared__ float t[32][33];
    int b = blockIdx.z;
    int n0 = blockIdx.x * 32, c0 = blockIdx.y * 32;
    int n = n0 + threadIdx.y, c = c0 + threadIdx.x;
    float v = y[((size_t)b * NPTS + n) * CO + c];
    v = fmaxf(v * scale[c] + shift[c], 0.f);
    t[threadIdx.y][threadIdx.x] = v;
    __syncthreads();
    out[((size_t)b * CO + c0 + threadIdx.y) * NPTS + n0 + threadIdx.x] = t[threadIdx.x][threadIdx.y];
}

// ---------------- launch -----------------------------------------------------------
extern "C" void kernel_launch(void* const* d_in, const int* in_sizes, int n_in,
                              void* d_out, int out_size) {
    const float* xyz1    = (const float*)d_in[0];
    const float* xyz2    = (const float*)d_in[1];
    const float* points1 = (const float*)d_in[2];
    const float* points2 = (const float*)d_in[3];
    const float* W1      = (const float*)d_in[4];
    const float* g1      = (const float*)d_in[6];
    const float* beta1   = (const float*)d_in[7];
    const float* W2      = (const float*)d_in[8];
    const float* g2      = (const float*)d_in[10];
    const float* beta2   = (const float*)d_in[11];
    float* out = (float*)d_out;

    float *feat, *y, *a2, *w3, *scale, *shift;
    unsigned short *Bhi1, *Blo1, *Bhi2, *Blo2;
    int* idx3;
    double* stats;
    cudaGetSymbolAddress((void**)&feat, g_feat);
    cudaGetSymbolAddress((void**)&y, g_y);
    cudaGetSymbolAddress((void**)&a2, g_a2);
    cudaGetSymbolAddress((void**)&Bhi1, g_Bhi1);
    cudaGetSymbolAddress((void**)&Blo1, g_Blo1);
    cudaGetSymbolAddress((void**)&Bhi2, g_Bhi2);
    cudaGetSymbolAddress((void**)&Blo2, g_Blo2);
    cudaGetSymbolAddress((void**)&w3, g_w3);
    cudaGetSymbolAddress((void**)&idx3, g_idx3);
    cudaGetSymbolAddress((void**)&stats, g_stats);
    cudaGetSymbolAddress((void**)&scale, g_scale);
    cudaGetSymbolAddress((void**)&shift, g_shift);

    zero_stats_kernel<<<1, 1024>>>(stats);
    prep_w_kernel<<<(CO * CF) / 256, 256>>>(W1, Bhi1, Blo1, CO * CF);
    prep_w_kernel<<<(CO * CO) / 256, 256>>>(W2, Bhi2, Blo2, CO * CO);

    three_nn_kernel<<<dim3(NPTS / 256, BATCH), 256>>>(xyz1, xyz2, idx3, w3);
    build_feat_kernel<<<dim3(NPTS, BATCH), 256>>>(points1, points2, idx3, w3, feat);

    // layer 1: split-bf16 HMMA GEMM (K=768) + BN + ReLU
    mma_gemm_kernel<<<dim3(CO / 128, RTOT / 128), 512>>>(feat, Bhi1, Blo1, y, CF);
    stats_kernel<<<256, 256>>>(y, stats);
    finalize_kernel<<<1, 256>>>(stats, g1, beta1, scale, shift);
    bn_relu_kernel<<<(RTOT * CO / 4) / 256, 256>>>((const float4*)y, scale, shift, (float4*)a2);

    // layer 2: split-bf16 HMMA GEMM (K=256) + BN + ReLU + transpose
    mma_gemm_kernel<<<dim3(CO / 128, RTOT / 128), 512>>>(a2, Bhi2, Blo2, y, CO);
    stats_kernel<<<256, 256>>>(y, stats + 512);
    finalize_kernel<<<1, 256>>>(stats + 512, g2, beta2, scale + 256, shift + 256);
    bn_relu_tr_kernel<<<dim3(NPTS / 32, CO / 32, BATCH), dim3(32, 32)>>>(y, scale + 256, shift + 256, out);
}

// round 4
// speedup vs baseline: 1.8384x; 1.2204x over previous
#include <cuda_runtime.h>
#include <cuda_bf16.h>
#include <cstdint>

// Problem constants
#define BATCH 16
#define NPTS  4096
#define MPTS  1024
#define C1    256
#define C2    512
#define CO    256
#define RTOT  65536
#define NZ    4
#define CHM   (MPTS / NZ)   // 256

// ---------------- scratch (static __device__ globals; no allocation) ----------
__device__ float  g_y  [(size_t)RTOT * CO];
__device__ float  g_y2 [(size_t)RTOT * CO];
__device__ unsigned short g_Bhi1[CO * 768];
__device__ unsigned short g_Blo1[CO * 768];
__device__ unsigned short g_Bhi2[CO * 256];
__device__ unsigned short g_Blo2[CO * 256];
__device__ float  g_pd [(size_t)NZ * RTOT * 3];
__device__ int    g_pi [(size_t)NZ * RTOT * 3];
__device__ float  g_w3 [RTOT * 3];
__device__ int    g_idx3[RTOT * 3];
__device__ double g_stats[1024];
__device__ float  g_scale[512];
__device__ float  g_shift[512];

// ---------------- helpers ---------------------------------------------------------
__device__ __forceinline__ uint32_t smem_u32(const void* p) {
    uint32_t a;
    asm("{ .reg .u64 t; cvta.to.shared.u64 t, %1; cvt.u32.u64 %0, t; }" : "=r"(a) : "l"(p));
    return a;
}

__device__ __forceinline__ void cpa16(uint32_t s, const void* g) {
    asm volatile("cp.async.ca.shared.global [%0], [%1], 16;" :: "r"(s), "l"(g));
}
__device__ __forceinline__ void cpa8(uint32_t s, const void* g) {
    asm volatile("cp.async.ca.shared.global [%0], [%1], 8;" :: "r"(s), "l"(g));
}
#define CP_COMMIT() asm volatile("cp.async.commit_group;" ::: "memory")
#define CP_WAIT0()  asm volatile("cp.async.wait_group 0;" ::: "memory")

#define LDSM4(r, addr) \
    asm volatile("ldmatrix.sync.aligned.m8n8.x4.shared.b16 {%0,%1,%2,%3}, [%4];" \
                 : "=r"((r)[0]), "=r"((r)[1]), "=r"((r)[2]), "=r"((r)[3]) : "r"(addr))

#define MMA16816(d, a, b0, b1) \
    asm volatile("mma.sync.aligned.m16n8k16.row.col.f32.bf16.bf16.f32 " \
                 "{%0,%1,%2,%3}, {%4,%5,%6,%7}, {%8,%9}, {%0,%1,%2,%3};" \
                 : "+f"((d)[0]), "+f"((d)[1]), "+f"((d)[2]), "+f"((d)[3]) \
                 : "r"((a)[0]), "r"((a)[1]), "r"((a)[2]), "r"((a)[3]), "r"(b0), "r"(b1))

__device__ __forceinline__ void split4(float4 v, uint2& hi, uint2& lo) {
    __nv_bfloat16 h0 = __float2bfloat16_rn(v.x);
    __nv_bfloat16 h1 = __float2bfloat16_rn(v.y);
    __nv_bfloat16 h2 = __float2bfloat16_rn(v.z);
    __nv_bfloat16 h3 = __float2bfloat16_rn(v.w);
    __nv_bfloat16 l0 = __float2bfloat16_rn(v.x - __bfloat162float(h0));
    __nv_bfloat16 l1 = __float2bfloat16_rn(v.y - __bfloat162float(h1));
    __nv_bfloat16 l2 = __float2bfloat16_rn(v.z - __bfloat162float(h2));
    __nv_bfloat16 l3 = __float2bfloat16_rn(v.w - __bfloat162float(h3));
    hi.x = (uint32_t)__bfloat16_as_ushort(h0) | ((uint32_t)__bfloat16_as_ushort(h1) << 16);
    hi.y = (uint32_t)__bfloat16_as_ushort(h2) | ((uint32_t)__bfloat16_as_ushort(h3) << 16);
    lo.x = (uint32_t)__bfloat16_as_ushort(l0) | ((uint32_t)__bfloat16_as_ushort(l1) << 16);
    lo.y = (uint32_t)__bfloat16_as_ushort(l2) | ((uint32_t)__bfloat16_as_ushort(l3) << 16);
}

// ---------------- small utility kernels -----------------------------------------
__global__ void zero_stats_kernel(double* stats) { stats[threadIdx.x] = 0.0; }

__global__ void prep_w_kernel(const float* __restrict__ W,
                              unsigned short* __restrict__ Bhi,
                              unsigned short* __restrict__ Blo, int total) {
    int idx = blockIdx.x * 256 + threadIdx.x;
    if (idx >= total) return;
    float v = W[idx];
    __nv_bfloat16 hi = __float2bfloat16_rn(v);
    __nv_bfloat16 lo = __float2bfloat16_rn(v - __bfloat162float(hi));
    Bhi[idx] = __bfloat16_as_ushort(hi);
    Blo[idx] = __bfloat16_as_ushort(lo);
}

// ---------------- 3-NN: partial over MPTS chunks, then merge ---------------------
__global__ void three_nn_part_kernel(const float* __restrict__ xyz1,
                                     const float* __restrict__ xyz2,
                                     float* __restrict__ pd, int* __restrict__ pi) {
    __shared__ float sx[CHM], sy[CHM], sz[CHM];
    int b = blockIdx.y, ch = blockIdx.z;
    int tid = threadIdx.x;
    const float* p2 = xyz2 + ((size_t)b * MPTS + ch * CHM) * 3;
    sx[tid] = p2[tid * 3 + 0];
    sy[tid] = p2[tid * 3 + 1];
    sz[tid] = p2[tid * 3 + 2];
    __syncthreads();

    int n = blockIdx.x * 256 + tid;
    size_t r = (size_t)b * NPTS + n;
    float x = xyz1[r * 3 + 0], y = xyz1[r * 3 + 1], z = xyz1[r * 3 + 2];

    float d0 = 1e30f, d1 = 1e30f, d2v = 1e30f;
    int   i0 = 0, i1 = 0, i2 = 0;
    #pragma unroll 4
    for (int j = 0; j < CHM; j++) {
        float dx = x - sx[j], dy = y - sy[j], dz = z - sz[j];
        float d = dx * dx + dy * dy + dz * dz;
        if (d < d0)        { d2v = d1; i2 = i1; d1 = d0; i1 = i0; d0 = d; i0 = j; }
        else if (d < d1)   { d2v = d1; i2 = i1; d1 = d;  i1 = j; }
        else if (d < d2v)  { d2v = d;  i2 = j; }
    }
    size_t o = ((size_t)ch * RTOT + r) * 3;
    pd[o + 0] = d0;  pd[o + 1] = d1;  pd[o + 2] = d2v;
    pi[o + 0] = ch * CHM + i0;
    pi[o + 1] = ch * CHM + i1;
    pi[o + 2] = ch * CHM + i2;
}

__global__ void three_nn_merge_kernel(const float* __restrict__ pd,
                                      const int* __restrict__ pi,
                                      int* __restrict__ idx, float* __restrict__ w) {
    size_t r = (size_t)blockIdx.x * 256 + threadIdx.x;
    float d0 = 1e30f, d1 = 1e30f, d2v = 1e30f;
    int   i0 = 0, i1 = 0, i2 = 0;
    #pragma unroll
    for (int ch = 0; ch < NZ; ch++) {
        size_t o = ((size_t)ch * RTOT + r) * 3;
        #pragma unroll
        for (int k = 0; k < 3; k++) {
            float d = pd[o + k];
            int   ii = pi[o + k];
            if (d < d0)        { d2v = d1; i2 = i1; d1 = d0; i1 = i0; d0 = d; i0 = ii; }
            else if (d < d1)   { d2v = d1; i2 = i1; d1 = d;  i1 = ii; }
            else if (d < d2v)  { d2v = d;  i2 = ii; }
        }
    }
    float c0 = fminf(fmaxf(d0, 0.f), 1e-10f);
    float c1 = fminf(fmaxf(d1, 0.f), 1e-10f);
    float c2 = fminf(fmaxf(d2v, 0.f), 1e-10f);
    float v0 = 1.f / c0, v1 = 1.f / c1, v2 = 1.f / c2;
    float s = v0 + v1 + v2;
    w[r * 3 + 0] = v0 / s;
    w[r * 3 + 1] = v1 / s;
    w[r * 3 + 2] = v2 / s;
    idx[r * 3 + 0] = i0;
    idx[r * 3 + 1] = i1;
    idx[r * 3 + 2] = i2;
}

// ---------------- fused split-bf16 HMMA GEMM ------------------------------------
// MODE 0: A[r][k] = k<512 ? interp(points2 gather) : points1   (K=768)
// MODE 1: A[r][k] = relu(y1[r][k]*scale[k]+shift[k])           (K=256)
// CTA tile 128M x 256N (full N), 16 warps (4M x 4N), warp tile 32x64.
// Epilogue: write Y + per-channel sum/sumsq (smem reduce -> double atomics).
#define RS    40      // bf16 smem row stride (elements)
#define RSRAW 36      // raw fp32 staging row stride (elements)

// smem layout (bytes)
#define SZ_ABUF 10240                 // 128*RS*2
#define SZ_BBUF 20480                 // 256*RS*2
#define OFF_A    0                    // Ahi[2] then Alo[2]
#define OFF_B    40960                // Bhi[2] then Blo[2]
#define OFF_RAW  122880               // 3 regions x 18432
#define OFF_IDX  178176
#define OFF_W    179712
#define OFF_SC   181248
#define OFF_SH   182272
#define OFF_SUM  183296
#define OFF_SQ   184320
#define SM_TOTAL 185344

template<int MODE>
__global__ void __launch_bounds__(512, 1)
fused_gemm_kernel(const float* __restrict__ P1,      // MODE0: points1
                  const float* __restrict__ P2,      // MODE0: points2 ; MODE1: y1
                  const int* __restrict__ idx3,
                  const float* __restrict__ w3,
                  const unsigned short* __restrict__ Bhi,
                  const unsigned short* __restrict__ Blo,
                  const float* __restrict__ scale,
                  const float* __restrict__ shift,
                  float* __restrict__ Y,
                  double* __restrict__ stats) {
    constexpr int K   = MODE ? 256 : 768;
    constexpr int KCH = K / 32;
    extern __shared__ char sm[];
    uint32_t sb = smem_u32(sm);

    int tid = threadIdx.x, lane = tid & 31, wid = tid >> 5;
    int wm = wid & 3, wn = wid >> 2;
    int rbase = blockIdx.x * 128;
    int b = rbase >> 12;
    int nbase = rbase & 4095;

    if (MODE == 0) {
        if (tid < 384) {
            ((int*)(sm + OFF_IDX))[tid] = idx3[(size_t)rbase * 3 + tid];
            ((float*)(sm + OFF_W))[tid] = w3[(size_t)rbase * 3 + tid];
        }
    } else {
        if (tid < 256) {
            ((float*)(sm + OFF_SC))[tid] = scale[tid];
            ((float*)(sm + OFF_SH))[tid] = shift[tid];
        }
    }
    if (tid < 256) {
        ((float*)(sm + OFF_SUM))[tid] = 0.f;
        ((float*)(sm + OFF_SQ))[tid]  = 0.f;
    }
    __syncthreads();

    int aRow0 = tid >> 3, aQ = tid & 7;   // A slot base: rows aRow0, aRow0+64

    auto cp_chunk = [&](int c, int s) {
        int k0 = c * 32;
        #pragma unroll
        for (int it = 0; it < 4; it++) {   // B: 2048 8B slots per matrix
            int idx = it * 512 + tid;
            int row = idx >> 3, q = idx & 7;
            uint32_t d = sb + OFF_B + s * SZ_BBUF + (uint32_t)(row * RS + q * 4) * 2;
            cpa8(d,                 Bhi + (size_t)row * K + k0 + q * 4);
            cpa8(d + 2 * SZ_BBUF,   Blo + (size_t)row * K + k0 + q * 4);
        }
        #pragma unroll
        for (int it = 0; it < 2; it++) {   // A raw: 1024 16B slots
            int row = aRow0 + it * 64;
            uint32_t d = sb + OFF_RAW + (uint32_t)(row * RSRAW + aQ * 4) * 4;
            if (MODE == 0) {
                if (k0 < 512) {
                    const int* si = (const int*)(sm + OFF_IDX) + row * 3;
                    const float* src = P2 + (size_t)b * MPTS * C2 + k0 + aQ * 4;
                    cpa16(d,         src + (size_t)si[0] * C2);
                    cpa16(d + 18432, src + (size_t)si[1] * C2);
                    cpa16(d + 36864, src + (size_t)si[2] * C2);
                } else {
                    cpa16(d, P1 + ((size_t)b * NPTS + nbase + row) * C1 + (k0 - 512) + aQ * 4);
                }
            } else {
                cpa16(d, P2 + (size_t)(rbase + row) * K + k0 + aQ * 4);
            }
        }
        CP_COMMIT();
    };

    auto convert_chunk = [&](int c, int s) {
        int k0 = c * 32;
        #pragma unroll
        for (int it = 0; it < 2; it++) {
            int row = aRow0 + it * 64;
            uint32_t roff = (uint32_t)(row * RSRAW + aQ * 4) * 4;
            float4 v = *(const float4*)(sm + OFF_RAW + roff);
            if (MODE == 0) {
                if (k0 < 512) {
                    float4 v1 = *(const float4*)(sm + OFF_RAW + 18432 + roff);
                    float4 v2 = *(const float4*)(sm + OFF_RAW + 36864 + roff);
                    const float* wp = (const float*)(sm + OFF_W) + row * 3;
                    float w0 = wp[0], w1 = wp[1], w2 = wp[2];
                    v.x = w0 * v.x + w1 * v1.x + w2 * v2.x;
                    v.y = w0 * v.y + w1 * v1.y + w2 * v2.y;
                    v.z = w0 * v.z + w1 * v1.z + w2 * v2.z;
                    v.w = w0 * v.w + w1 * v1.w + w2 * v2.w;
                }
            } else {
                const float* sc = (const float*)(sm + OFF_SC) + k0 + aQ * 4;
                const float* sh = (const float*)(sm + OFF_SH) + k0 + aQ * 4;
                v.x = fmaxf(v.x * sc[0] + sh[0], 0.f);
                v.y = fmaxf(v.y * sc[1] + sh[1], 0.f);
                v.z = fmaxf(v.z * sc[2] + sh[2], 0.f);
                v.w = fmaxf(v.w * sc[3] + sh[3], 0.f);
            }
            uint2 hi, lo;
            split4(v, hi, lo);
            uint32_t aoff = (uint32_t)(row * RS + aQ * 4) * 2;
            *(uint2*)(sm + OFF_A + s * SZ_ABUF + aoff) = hi;
            *(uint2*)(sm + OFF_A + 2 * SZ_ABUF + s * SZ_ABUF + aoff) = lo;
        }
    };

    cp_chunk(0, 0);
    CP_WAIT0();
    convert_chunk(0, 0);
    __syncthreads();

    float acc[2][8][4] = {};

    for (int c = 0; c < KCH; c++) {
        int s = c & 1;
        if (c + 1 < KCH) cp_chunk(c + 1, 1 - s);

        uint32_t sAhi = sb + OFF_A + s * SZ_ABUF;
        uint32_t sAlo = sAhi + 2 * SZ_ABUF;
        uint32_t sBhi = sb + OFF_B + s * SZ_BBUF;
        uint32_t sBlo = sBhi + 2 * SZ_BBUF;

        #pragma unroll
        for (int ks = 0; ks < 2; ks++) {
            uint32_t ah[2][4], al[2][4];
            int arow = wm * 32 + (lane & 15);
            int akoff = ks * 16 + (lane >> 4) * 8;
            LDSM4(ah[0], sAhi + (uint32_t)((arow)      * RS + akoff) * 2);
            LDSM4(ah[1], sAhi + (uint32_t)((arow + 16) * RS + akoff) * 2);
            LDSM4(al[0], sAlo + (uint32_t)((arow)      * RS + akoff) * 2);
            LDSM4(al[1], sAlo + (uint32_t)((arow + 16) * RS + akoff) * 2);
            #pragma unroll
            for (int h = 0; h < 2; h++) {
                uint32_t bh[2][4], bl[2][4];
                int brow = wn * 64 + h * 32 + (lane & 7) + ((lane >> 4) & 1) * 8;
                int bkoff = ks * 16 + ((lane >> 3) & 1) * 8;
                LDSM4(bh[0], sBhi + (uint32_t)((brow)      * RS + bkoff) * 2);
                LDSM4(bh[1], sBhi + (uint32_t)((brow + 16) * RS + bkoff) * 2);
                LDSM4(bl[0], sBlo + (uint32_t)((brow)      * RS + bkoff) * 2);
                LDSM4(bl[1], sBlo + (uint32_t)((brow + 16) * RS + bkoff) * 2);
                #pragma unroll
                for (int mi = 0; mi < 2; mi++) {
                    #pragma unroll
                    for (int j = 0; j < 2; j++) {
                        float* a0 = acc[mi][h * 4 + j * 2 + 0];
                        float* a1 = acc[mi][h * 4 + j * 2 + 1];
                        MMA16816(a0, ah[mi], bh[j][0], bh[j][1]);
                        MMA16816(a1, ah[mi], bh[j][2], bh[j][3]);
                        MMA16816(a0, ah[mi], bl[j][0], bl[j][1]);
                        MMA16816(a1, ah[mi], bl[j][2], bl[j][3]);
                        MMA16816(a0, al[mi], bh[j][0], bh[j][1]);
                        MMA16816(a1, al[mi], bh[j][2], bh[j][3]);
                    }
                }
            }
        }
        if (c + 1 < KCH) {
            CP_WAIT0();
            convert_chunk(c + 1, 1 - s);
        }
        __syncthreads();
    }

    // epilogue: Y write + per-channel partial stats
    int rr = rbase + wm * 32 + (lane >> 2);
    int cc0 = wn * 64 + (lane & 3) * 2;
    float* ssum = (float*)(sm + OFF_SUM);
    float* ssq  = (float*)(sm + OFF_SQ);

    #pragma unroll
    for (int mi = 0; mi < 2; mi++) {
        #pragma unroll
        for (int ni = 0; ni < 8; ni++) {
            int col = cc0 + (ni >> 2) * 32 + ((ni >> 1) & 1) * 16 + (ni & 1) * 8;
            float* a = acc[mi][ni];
            *(float2*)(Y + (size_t)(rr + mi * 16)     * CO + col) = make_float2(a[0], a[1]);
            *(float2*)(Y + (size_t)(rr + mi * 16 + 8) * CO + col) = make_float2(a[2], a[3]);
        }
    }
    #pragma unroll
    for (int ni = 0; ni < 8; ni++) {
        int col = cc0 + (ni >> 2) * 32 + ((ni >> 1) & 1) * 16 + (ni & 1) * 8;
        float s0 = acc[0][ni][0] + acc[0][ni][2] + acc[1][ni][0] + acc[1][ni][2];
        float s1 = acc[0][ni][1] + acc[0][ni][3] + acc[1][ni][1] + acc[1][ni][3];
        float q0 = acc[0][ni][0] * acc[0][ni][0] + acc[0][ni][2] * acc[0][ni][2]
                 + acc[1][ni][0] * acc[1][ni][0] + acc[1][ni][2] * acc[1][ni][2];
        float q1 = acc[0][ni][1] * acc[0][ni][1] + acc[0][ni][3] * acc[0][ni][3]
                 + acc[1][ni][1] * acc[1][ni][1] + acc[1][ni][3] * acc[1][ni][3];
        atomicAdd(&ssum[col], s0);
        atomicAdd(&ssq[col],  q0);
        atomicAdd(&ssum[col + 1], s1);
        atomicAdd(&ssq[col + 1],  q1);
    }
    __syncthreads();
    if (tid < 256) {
        atomicAdd(&stats[tid],      (double)ssum[tid]);
        atomicAdd(&stats[CO + tid], (double)ssq[tid]);
    }
}

// ---------------- finalize BN params ----------------------------------------------
__global__ void finalize_kernel(const double* __restrict__ sums,
                                const float* __restrict__ g, const float* __restrict__ beta,
                                float* __restrict__ scale, float* __restrict__ shift) {
    int c = threadIdx.x;
    double mean = sums[c] * (1.0 / RTOT);
    double var = sums[CO + c] * (1.0 / RTOT) - mean * mean;
    float sc = g[c] * rsqrtf((float)var + 1e-5f);
    scale[c] = sc;
    shift[c] = beta[c] - (float)mean * sc;
}

// ---------------- final BN + ReLU + transpose to (b, c, n) -------------------------
__global__ void bn_relu_tr_kernel(const float* __restrict__ y,
                                  const float* __restrict__ scale, const float* __restrict__ shift,
                                  float* __restrict__ out) {
    __shared__ float t[32][33];
    int b = blockIdx.z;
    int n0 = blockIdx.x * 32, c0 = blockIdx.y * 32;
    int n = n0 + threadIdx.y, c = c0 + threadIdx.x;
    float v = y[((size_t)b * NPTS + n) * CO + c];
    v = fmaxf(v * scale[c] + shift[c], 0.f);
    t[threadIdx.y][threadIdx.x] = v;
    __syncthreads();
    out[((size_t)b * CO + c0 + threadIdx.y) * NPTS + n0 + threadIdx.x] = t[threadIdx.x][threadIdx.y];
}

// ---------------- launch -----------------------------------------------------------
extern "C" void kernel_launch(void* const* d_in, const int* in_sizes, int n_in,
                              void* d_out, int out_size) {
    const float* xyz1    = (const float*)d_in[0];
    const float* xyz2    = (const float*)d_in[1];
    const float* points1 = (const float*)d_in[2];
    const float* points2 = (const float*)d_in[3];
    const float* W1      = (const float*)d_in[4];
    const float* g1      = (const float*)d_in[6];
    const float* beta1   = (const float*)d_in[7];
    const float* W2      = (const float*)d_in[8];
    const float* g2      = (const float*)d_in[10];
    const float* beta2   = (const float*)d_in[11];
    float* out = (float*)d_out;

    float *y, *y2, *pd, *w3, *scale, *shift;
    unsigned short *Bhi1, *Blo1, *Bhi2, *Blo2;
    int *pi, *idx3;
    double* stats;
    cudaGetSymbolAddress((void**)&y, g_y);
    cudaGetSymbolAddress((void**)&y2, g_y2);
    cudaGetSymbolAddress((void**)&Bhi1, g_Bhi1);
    cudaGetSymbolAddress((void**)&Blo1, g_Blo1);
    cudaGetSymbolAddress((void**)&Bhi2, g_Bhi2);
    cudaGetSymbolAddress((void**)&Blo2, g_Blo2);
    cudaGetSymbolAddress((void**)&pd, g_pd);
    cudaGetSymbolAddress((void**)&pi, g_pi);
    cudaGetSymbolAddress((void**)&w3, g_w3);
    cudaGetSymbolAddress((void**)&idx3, g_idx3);
    cudaGetSymbolAddress((void**)&stats, g_stats);
    cudaGetSymbolAddress((void**)&scale, g_scale);
    cudaGetSymbolAddress((void**)&shift, g_shift);

    cudaFuncSetAttribute(fused_gemm_kernel<0>, cudaFuncAttributeMaxDynamicSharedMemorySize, SM_TOTAL);
    cudaFuncSetAttribute(fused_gemm_kernel<1>, cudaFuncAttributeMaxDynamicSharedMemorySize, SM_TOTAL);

    zero_stats_kernel<<<1, 1024>>>(stats);
    prep_w_kernel<<<(CO * 768) / 256, 256>>>(W1, Bhi1, Blo1, CO * 768);
    prep_w_kernel<<<(CO * 256) / 256, 256>>>(W2, Bhi2, Blo2, CO * 256);

    three_nn_part_kernel<<<dim3(NPTS / 256, BATCH, NZ), 256>>>(xyz1, xyz2, pd, pi);
    three_nn_merge_kernel<<<RTOT / 256, 256>>>(pd, pi, idx3, w3);

    // layer 1: fused gather + split-bf16 GEMM (K=768) + stats
    fused_gemm_kernel<0><<<RTOT / 128, 512, SM_TOTAL>>>(
        points1, points2, idx3, w3, Bhi1, Blo1, nullptr, nullptr, y, stats);
    finalize_kernel<<<1, 256>>>(stats, g1, beta1, scale, shift);

    // layer 2: fused BN+ReLU + split-bf16 GEMM (K=256) + stats
    fused_gemm_kernel<1><<<RTOT / 128, 512, SM_TOTAL>>>(
        nullptr, y, nullptr, nullptr, Bhi2, Blo2, scale, shift, y2, stats + 512);
    finalize_kernel<<<1, 256>>>(stats + 512, g2, beta2, scale + 256, shift + 256);

    bn_relu_tr_kernel<<<dim3(NPTS / 32, CO / 32, BATCH), dim3(32, 32)>>>(
        y2, scale + 256, shift + 256, out);
}

// round 5
// speedup vs baseline: 1.9140x; 1.0411x over previous
#include <cuda_runtime.h>
#include <cuda_bf16.h>
#include <cstdint>

// Problem constants
#define BATCH 16
#define NPTS  4096
#define MPTS  1024
#define C1    256
#define C2    512
#define CO    256
#define RTOT  65536
#define NZ    4
#define CHM   (MPTS / NZ)   // 256

// ---------------- scratch (static __device__ globals; no allocation) ----------
__device__ float  g_y  [(size_t)RTOT * CO];
__device__ float  g_y2 [(size_t)RTOT * CO];
__device__ unsigned short g_Bhi1[CO * 768];
__device__ unsigned short g_Blo1[CO * 768];
__device__ unsigned short g_Bhi2[CO * 256];
__device__ unsigned short g_Blo2[CO * 256];
__device__ float  g_pd [(size_t)NZ * RTOT * 3];
__device__ int    g_pi [(size_t)NZ * RTOT * 3];
__device__ float  g_w3 [RTOT * 3];
__device__ int    g_idx3[RTOT * 3];
__device__ double g_stats[1024];
__device__ float  g_scale[512];
__device__ float  g_shift[512];

// ---------------- helpers ---------------------------------------------------------
__device__ __forceinline__ uint32_t smem_u32(const void* p) {
    uint32_t a;
    asm("{ .reg .u64 t; cvta.to.shared.u64 t, %1; cvt.u32.u64 %0, t; }" : "=r"(a) : "l"(p));
    return a;
}

__device__ __forceinline__ void cpa16(uint32_t s, const void* g) {
    asm volatile("cp.async.ca.shared.global [%0], [%1], 16;" :: "r"(s), "l"(g));
}
#define CP_COMMIT() asm volatile("cp.async.commit_group;" ::: "memory")
#define CP_WAIT0()  asm volatile("cp.async.wait_group 0;" ::: "memory")

#define LDSM4(r, addr) \
    asm volatile("ldmatrix.sync.aligned.m8n8.x4.shared.b16 {%0,%1,%2,%3}, [%4];" \
                 : "=r"((r)[0]), "=r"((r)[1]), "=r"((r)[2]), "=r"((r)[3]) : "r"(addr))

#define MMA16816(d, a, b0, b1) \
    asm volatile("mma.sync.aligned.m16n8k16.row.col.f32.bf16.bf16.f32 " \
                 "{%0,%1,%2,%3}, {%4,%5,%6,%7}, {%8,%9}, {%0,%1,%2,%3};" \
                 : "+f"((d)[0]), "+f"((d)[1]), "+f"((d)[2]), "+f"((d)[3]) \
                 : "r"((a)[0]), "r"((a)[1]), "r"((a)[2]), "r"((a)[3]), "r"(b0), "r"(b1))

__device__ __forceinline__ void split4(float4 v, uint2& hi, uint2& lo) {
    __nv_bfloat16 h0 = __float2bfloat16_rn(v.x);
    __nv_bfloat16 h1 = __float2bfloat16_rn(v.y);
    __nv_bfloat16 h2 = __float2bfloat16_rn(v.z);
    __nv_bfloat16 h3 = __float2bfloat16_rn(v.w);
    __nv_bfloat16 l0 = __float2bfloat16_rn(v.x - __bfloat162float(h0));
    __nv_bfloat16 l1 = __float2bfloat16_rn(v.y - __bfloat162float(h1));
    __nv_bfloat16 l2 = __float2bfloat16_rn(v.z - __bfloat162float(h2));
    __nv_bfloat16 l3 = __float2bfloat16_rn(v.w - __bfloat162float(h3));
    hi.x = (uint32_t)__bfloat16_as_ushort(h0) | ((uint32_t)__bfloat16_as_ushort(h1) << 16);
    hi.y = (uint32_t)__bfloat16_as_ushort(h2) | ((uint32_t)__bfloat16_as_ushort(h3) << 16);
    lo.x = (uint32_t)__bfloat16_as_ushort(l0) | ((uint32_t)__bfloat16_as_ushort(l1) << 16);
    lo.y = (uint32_t)__bfloat16_as_ushort(l2) | ((uint32_t)__bfloat16_as_ushort(l3) << 16);
}

// ---------------- small utility kernels -----------------------------------------
__global__ void zero_stats_kernel(double* stats) { stats[threadIdx.x] = 0.0; }

__global__ void prep_w_kernel(const float* __restrict__ W,
                              unsigned short* __restrict__ Bhi,
                              unsigned short* __restrict__ Blo, int total) {
    int idx = blockIdx.x * 256 + threadIdx.x;
    if (idx >= total) return;
    float v = W[idx];
    __nv_bfloat16 hi = __float2bfloat16_rn(v);
    __nv_bfloat16 lo = __float2bfloat16_rn(v - __bfloat162float(hi));
    Bhi[idx] = __bfloat16_as_ushort(hi);
    Blo[idx] = __bfloat16_as_ushort(lo);
}

// ---------------- 3-NN: partial over MPTS chunks, then merge ---------------------
__global__ void three_nn_part_kernel(const float* __restrict__ xyz1,
                                     const float* __restrict__ xyz2,
                                     float* __restrict__ pd, int* __restrict__ pi) {
    __shared__ float sx[CHM], sy[CHM], sz[CHM];
    int b = blockIdx.y, ch = blockIdx.z;
    int tid = threadIdx.x;
    const float* p2 = xyz2 + ((size_t)b * MPTS + ch * CHM) * 3;
    sx[tid] = p2[tid * 3 + 0];
    sy[tid] = p2[tid * 3 + 1];
    sz[tid] = p2[tid * 3 + 2];
    __syncthreads();

    int n = blockIdx.x * 256 + tid;
    size_t r = (size_t)b * NPTS + n;
    float x = xyz1[r * 3 + 0], y = xyz1[r * 3 + 1], z = xyz1[r * 3 + 2];

    float d0 = 1e30f, d1 = 1e30f, d2v = 1e30f;
    int   i0 = 0, i1 = 0, i2 = 0;
    #pragma unroll 4
    for (int j = 0; j < CHM; j++) {
        float dx = x - sx[j], dy = y - sy[j], dz = z - sz[j];
        float d = dx * dx + dy * dy + dz * dz;
        if (d < d0)        { d2v = d1; i2 = i1; d1 = d0; i1 = i0; d0 = d; i0 = j; }
        else if (d < d1)   { d2v = d1; i2 = i1; d1 = d;  i1 = j; }
        else if (d < d2v)  { d2v = d;  i2 = j; }
    }
    size_t o = ((size_t)ch * RTOT + r) * 3;
    pd[o + 0] = d0;  pd[o + 1] = d1;  pd[o + 2] = d2v;
    pi[o + 0] = ch * CHM + i0;
    pi[o + 1] = ch * CHM + i1;
    pi[o + 2] = ch * CHM + i2;
}

__global__ void three_nn_merge_kernel(const float* __restrict__ pd,
                                      const int* __restrict__ pi,
                                      int* __restrict__ idx, float* __restrict__ w) {
    size_t r = (size_t)blockIdx.x * 256 + threadIdx.x;
    float d0 = 1e30f, d1 = 1e30f, d2v = 1e30f;
    int   i0 = 0, i1 = 0, i2 = 0;
    #pragma unroll
    for (int ch = 0; ch < NZ; ch++) {
        size_t o = ((size_t)ch * RTOT + r) * 3;
        #pragma unroll
        for (int k = 0; k < 3; k++) {
            float d = pd[o + k];
            int   ii = pi[o + k];
            if (d < d0)        { d2v = d1; i2 = i1; d1 = d0; i1 = i0; d0 = d; i0 = ii; }
            else if (d < d1)   { d2v = d1; i2 = i1; d1 = d;  i1 = ii; }
            else if (d < d2v)  { d2v = d;  i2 = ii; }
        }
    }
    float c0 = fminf(fmaxf(d0, 0.f), 1e-10f);
    float c1 = fminf(fmaxf(d1, 0.f), 1e-10f);
    float c2 = fminf(fmaxf(d2v, 0.f), 1e-10f);
    float v0 = 1.f / c0, v1 = 1.f / c1, v2 = 1.f / c2;
    float s = v0 + v1 + v2;
    w[r * 3 + 0] = v0 / s;
    w[r * 3 + 1] = v1 / s;
    w[r * 3 + 2] = v2 / s;
    idx[r * 3 + 0] = i0;
    idx[r * 3 + 1] = i1;
    idx[r * 3 + 2] = i2;
}

// ---------------- fused split-bf16 HMMA GEMM ------------------------------------
// MODE 0: A[r][k] = k<512 ? interp(points2 gather) : points1   (K=768)
// MODE 1: A[r][k] = relu(y1[r][k]*scale[k]+shift[k])           (K=256)
// CTA tile 128M x 256N, 8 warps (2M x 4N), warp tile 64x64 -> acc 128 regs.
#define RS    40      // bf16 smem row stride (elements)
#define RSRAW 36      // raw fp32 staging row stride (elements)

#define SZ_ABUF 10240                 // 128*RS*2
#define SZ_BBUF 20480                 // 256*RS*2
#define OFF_A    0                    // Ahi[2] then Alo[2]
#define OFF_B    40960                // Bhi[2] then Blo[2]
#define OFF_RAW  122880               // 3 regions x 18432
#define OFF_IDX  178176
#define OFF_W    179712
#define OFF_SC   181248
#define OFF_SH   182272
#define OFF_SUM  183296
#define OFF_SQ   184320
#define SM_TOTAL 185344

template<int MODE>
__global__ void __launch_bounds__(256, 1)
fused_gemm_kernel(const float* __restrict__ P1,
                  const float* __restrict__ P2,
                  const int* __restrict__ idx3,
                  const float* __restrict__ w3,
                  const unsigned short* __restrict__ Bhi,
                  const unsigned short* __restrict__ Blo,
                  const float* __restrict__ scale,
                  const float* __restrict__ shift,
                  float* __restrict__ Y,
                  double* __restrict__ stats) {
    constexpr int K   = MODE ? 256 : 768;
    constexpr int KCH = K / 32;
    extern __shared__ char sm[];
    uint32_t sb = smem_u32(sm);

    int tid = threadIdx.x, lane = tid & 31, wid = tid >> 5;
    int wm = wid & 1, wn = wid >> 1;          // 2M x 4N warps
    int rbase = blockIdx.x * 128;
    int b = rbase >> 12;
    int nbase = rbase & 4095;

    if (MODE == 0) {
        for (int i = tid; i < 384; i += 256) {
            ((int*)(sm + OFF_IDX))[i] = idx3[(size_t)rbase * 3 + i];
            ((float*)(sm + OFF_W))[i] = w3[(size_t)rbase * 3 + i];
        }
    } else {
        ((float*)(sm + OFF_SC))[tid] = scale[tid];
        ((float*)(sm + OFF_SH))[tid] = shift[tid];
    }
    ((float*)(sm + OFF_SUM))[tid] = 0.f;
    ((float*)(sm + OFF_SQ))[tid]  = 0.f;
    __syncthreads();

    auto cp_chunk = [&](int c, int s) {
        int k0 = c * 32;
        #pragma unroll
        for (int it = 0; it < 4; it++) {       // B: 1024 16B slots per matrix
            int slot = it * 256 + tid;
            int row = slot >> 2, q = slot & 3;
            uint32_t d = sb + OFF_B + s * SZ_BBUF + (uint32_t)(row * RS + q * 8) * 2;
            cpa16(d,               Bhi + (size_t)row * K + k0 + q * 8);
            cpa16(d + 2 * SZ_BBUF, Blo + (size_t)row * K + k0 + q * 8);
        }
        #pragma unroll
        for (int it = 0; it < 4; it++) {       // A raw: 1024 16B slots
            int slot = it * 256 + tid;
            int row = slot >> 3, q = slot & 7;
            uint32_t d = sb + OFF_RAW + (uint32_t)(row * RSRAW + q * 4) * 4;
            if (MODE == 0) {
                if (k0 < 512) {
                    const int* si = (const int*)(sm + OFF_IDX) + row * 3;
                    const float* src = P2 + (size_t)b * MPTS * C2 + k0 + q * 4;
                    cpa16(d,         src + (size_t)si[0] * C2);
                    cpa16(d + 18432, src + (size_t)si[1] * C2);
                    cpa16(d + 36864, src + (size_t)si[2] * C2);
                } else {
                    cpa16(d, P1 + ((size_t)b * NPTS + nbase + row) * C1 + (k0 - 512) + q * 4);
                }
            } else {
                cpa16(d, P2 + (size_t)(rbase + row) * K + k0 + q * 4);
            }
        }
        CP_COMMIT();
    };

    auto convert_chunk = [&](int c, int s) {
        int k0 = c * 32;
        #pragma unroll
        for (int it = 0; it < 4; it++) {
            int slot = it * 256 + tid;
            int row = slot >> 3, q = slot & 7;
            uint32_t roff = (uint32_t)(row * RSRAW + q * 4) * 4;
            float4 v = *(const float4*)(sm + OFF_RAW + roff);
            if (MODE == 0) {
                if (k0 < 512) {
                    float4 v1 = *(const float4*)(sm + OFF_RAW + 18432 + roff);
                    float4 v2 = *(const float4*)(sm + OFF_RAW + 36864 + roff);
                    const float* wp = (const float*)(sm + OFF_W) + row * 3;
                    float w0 = wp[0], w1 = wp[1], w2 = wp[2];
                    v.x = w0 * v.x + w1 * v1.x + w2 * v2.x;
                    v.y = w0 * v.y + w1 * v1.y + w2 * v2.y;
                    v.z = w0 * v.z + w1 * v1.z + w2 * v2.z;
                    v.w = w0 * v.w + w1 * v1.w + w2 * v2.w;
                }
            } else {
                const float* sc = (const float*)(sm + OFF_SC) + k0 + q * 4;
                const float* sh = (const float*)(sm + OFF_SH) + k0 + q * 4;
                v.x = fmaxf(v.x * sc[0] + sh[0], 0.f);
                v.y = fmaxf(v.y * sc[1] + sh[1], 0.f);
                v.z = fmaxf(v.z * sc[2] + sh[2], 0.f);
                v.w = fmaxf(v.w * sc[3] + sh[3], 0.f);
            }
            uint2 hi, lo;
            split4(v, hi, lo);
            uint32_t aoff = (uint32_t)(row * RS + q * 4) * 2;
            *(uint2*)(sm + OFF_A + s * SZ_ABUF + aoff) = hi;
            *(uint2*)(sm + OFF_A + 2 * SZ_ABUF + s * SZ_ABUF + aoff) = lo;
        }
    };

    cp_chunk(0, 0);
    CP_WAIT0();
    convert_chunk(0, 0);
    __syncthreads();

    float acc[4][8][4] = {};    // 4 m16 tiles x 8 n8 tiles x 4 regs = 128

    for (int c = 0; c < KCH; c++) {
        int s = c & 1;
        if (c + 1 < KCH) cp_chunk(c + 1, 1 - s);

        uint32_t sAhi = sb + OFF_A + s * SZ_ABUF;
        uint32_t sAlo = sAhi + 2 * SZ_ABUF;
        uint32_t sBhi = sb + OFF_B + s * SZ_BBUF;
        uint32_t sBlo = sBhi + 2 * SZ_BBUF;

        #pragma unroll
        for (int ks = 0; ks < 2; ks++) {
            int arow = wm * 64 + (lane & 15);
            int akoff = ks * 16 + (lane >> 4) * 8;
            int brow = wn * 64 + (lane & 7) + ((lane >> 4) & 1) * 8;
            int bkoff = ks * 16 + ((lane >> 3) & 1) * 8;

            uint32_t ah[4][4], al[4][4], bh[4][4];
            #pragma unroll
            for (int mi = 0; mi < 4; mi++) {
                LDSM4(ah[mi], sAhi + (uint32_t)((arow + mi * 16) * RS + akoff) * 2);
                LDSM4(al[mi], sAlo + (uint32_t)((arow + mi * 16) * RS + akoff) * 2);
            }
            #pragma unroll
            for (int jj = 0; jj < 4; jj++)
                LDSM4(bh[jj], sBhi + (uint32_t)((brow + jj * 16) * RS + bkoff) * 2);

            // hh: 32 independent MMAs
            #pragma unroll
            for (int mi = 0; mi < 4; mi++)
                #pragma unroll
                for (int jj = 0; jj < 4; jj++) {
                    MMA16816(acc[mi][jj * 2 + 0], ah[mi], bh[jj][0], bh[jj][1]);
                    MMA16816(acc[mi][jj * 2 + 1], ah[mi], bh[jj][2], bh[jj][3]);
                }
            // lh: Alo * Bhi
            #pragma unroll
            for (int mi = 0; mi < 4; mi++)
                #pragma unroll
                for (int jj = 0; jj < 4; jj++) {
                    MMA16816(acc[mi][jj * 2 + 0], al[mi], bh[jj][0], bh[jj][1]);
                    MMA16816(acc[mi][jj * 2 + 1], al[mi], bh[jj][2], bh[jj][3]);
                }
            // hl: Ahi * Blo (load bl late to cap live registers)
            uint32_t bl[4][4];
            #pragma unroll
            for (int jj = 0; jj < 4; jj++)
                LDSM4(bl[jj], sBlo + (uint32_t)((brow + jj * 16) * RS + bkoff) * 2);
            #pragma unroll
            for (int mi = 0; mi < 4; mi++)
                #pragma unroll
                for (int jj = 0; jj < 4; jj++) {
                    MMA16816(acc[mi][jj * 2 + 0], ah[mi], bl[jj][0], bl[jj][1]);
                    MMA16816(acc[mi][jj * 2 + 1], ah[mi], bl[jj][2], bl[jj][3]);
                }
        }
        if (c + 1 < KCH) {
            CP_WAIT0();
            convert_chunk(c + 1, 1 - s);
        }
        __syncthreads();
    }

    // epilogue: Y write + per-channel partial stats
    int rr = rbase + wm * 64 + (lane >> 2);
    int cc0 = wn * 64 + (lane & 3) * 2;
    float* ssum = (float*)(sm + OFF_SUM);
    float* ssq  = (float*)(sm + OFF_SQ);

    #pragma unroll
    for (int mi = 0; mi < 4; mi++) {
        #pragma unroll
        for (int nb = 0; nb < 8; nb++) {
            int col = cc0 + nb * 8;
            float* a = acc[mi][nb];
            *(float2*)(Y + (size_t)(rr + mi * 16)     * CO + col) = make_float2(a[0], a[1]);
            *(float2*)(Y + (size_t)(rr + mi * 16 + 8) * CO + col) = make_float2(a[2], a[3]);
        }
    }
    #pragma unroll
    for (int nb = 0; nb < 8; nb++) {
        int col = cc0 + nb * 8;
        float s0 = 0.f, s1 = 0.f, q0 = 0.f, q1 = 0.f;
        #pragma unroll
        for (int mi = 0; mi < 4; mi++) {
            float* a = acc[mi][nb];
            s0 += a[0] + a[2];
            s1 += a[1] + a[3];
            q0 += a[0] * a[0] + a[2] * a[2];
            q1 += a[1] * a[1] + a[3] * a[3];
        }
        atomicAdd(&ssum[col], s0);
        atomicAdd(&ssq[col],  q0);
        atomicAdd(&ssum[col + 1], s1);
        atomicAdd(&ssq[col + 1],  q1);
    }
    __syncthreads();
    atomicAdd(&stats[tid],      (double)ssum[tid]);
    atomicAdd(&stats[CO + tid], (double)ssq[tid]);
}

// ---------------- finalize BN params ----------------------------------------------
__global__ void finalize_kernel(const double* __restrict__ sums,
                                const float* __restrict__ g, const float* __restrict__ beta,
                                float* __restrict__ scale, float* __restrict__ shift) {
    int c = threadIdx.x;
    double mean = sums[c] * (1.0 / RTOT);
    double var = sums[CO + c] * (1.0 / RTOT) - mean * mean;
    float sc = g[c] * rsqrtf((float)var + 1e-5f);
    scale[c] = sc;
    shift[c] = beta[c] - (float)mean * sc;
}

// ---------------- final BN + ReLU + transpose to (b, c, n) -------------------------
__global__ void bn_relu_tr_kernel(const float* __restrict__ y,
                                  const float* __restrict__ scale, const float* __restrict__ shift,
                                  float* __restrict__ out) {
    __shared__ float t[32][33];
    int b = blockIdx.z;
    int n0 = blockIdx.x * 32, c0 = blockIdx.y * 32;
    int n = n0 + threadIdx.y, c = c0 + threadIdx.x;
    float v = y[((size_t)b * NPTS + n) * CO + c];
    v = fmaxf(v * scale[c] + shift[c], 0.f);
    t[threadIdx.y][threadIdx.x] = v;
    __syncthreads();
    out[((size_t)b * CO + c0 + threadIdx.y) * NPTS + n0 + threadIdx.x] = t[threadIdx.x][threadIdx.y];
}

// ---------------- launch -----------------------------------------------------------
extern "C" void kernel_launch(void* const* d_in, const int* in_sizes, int n_in,
                              void* d_out, int out_size) {
    const float* xyz1    = (const float*)d_in[0];
    const float* xyz2    = (const float*)d_in[1];
    const float* points1 = (const float*)d_in[2];
    const float* points2 = (const float*)d_in[3];
    const float* W1      = (const float*)d_in[4];
    const float* g1      = (const float*)d_in[6];
    const float* beta1   = (const float*)d_in[7];
    const float* W2      = (const float*)d_in[8];
    const float* g2      = (const float*)d_in[10];
    const float* beta2   = (const float*)d_in[11];
    float* out = (float*)d_out;

    float *y, *y2, *pd, *w3, *scale, *shift;
    unsigned short *Bhi1, *Blo1, *Bhi2, *Blo2;
    int *pi, *idx3;
    double* stats;
    cudaGetSymbolAddress((void**)&y, g_y);
    cudaGetSymbolAddress((void**)&y2, g_y2);
    cudaGetSymbolAddress((void**)&Bhi1, g_Bhi1);
    cudaGetSymbolAddress((void**)&Blo1, g_Blo1);
    cudaGetSymbolAddress((void**)&Bhi2, g_Bhi2);
    cudaGetSymbolAddress((void**)&Blo2, g_Blo2);
    cudaGetSymbolAddress((void**)&pd, g_pd);
    cudaGetSymbolAddress((void**)&pi, g_pi);
    cudaGetSymbolAddress((void**)&w3, g_w3);
    cudaGetSymbolAddress((void**)&idx3, g_idx3);
    cudaGetSymbolAddress((void**)&stats, g_stats);
    cudaGetSymbolAddress((void**)&scale, g_scale);
    cudaGetSymbolAddress((void**)&shift, g_shift);

    cudaFuncSetAttribute(fused_gemm_kernel<0>, cudaFuncAttributeMaxDynamicSharedMemorySize, SM_TOTAL);
    cudaFuncSetAttribute(fused_gemm_kernel<1>, cudaFuncAttributeMaxDynamicSharedMemorySize, SM_TOTAL);

    zero_stats_kernel<<<1, 1024>>>(stats);
    prep_w_kernel<<<(CO * 768) / 256, 256>>>(W1, Bhi1, Blo1, CO * 768);
    prep_w_kernel<<<(CO * 256) / 256, 256>>>(W2, Bhi2, Blo2, CO * 256);

    three_nn_part_kernel<<<dim3(NPTS / 256, BATCH, NZ), 256>>>(xyz1, xyz2, pd, pi);
    three_nn_merge_kernel<<<RTOT / 256, 256>>>(pd, pi, idx3, w3);

    // layer 1: fused gather + split-bf16 GEMM (K=768) + stats
    fused_gemm_kernel<0><<<RTOT / 128, 256, SM_TOTAL>>>(
        points1, points2, idx3, w3, Bhi1, Blo1, nullptr, nullptr, y, stats);
    finalize_kernel<<<1, 256>>>(stats, g1, beta1, scale, shift);

    // layer 2: fused BN+ReLU + split-bf16 GEMM (K=256) + stats
    fused_gemm_kernel<1><<<RTOT / 128, 256, SM_TOTAL>>>(
        nullptr, y, nullptr, nullptr, Bhi2, Blo2, scale, shift, y2, stats + 512);
    finalize_kernel<<<1, 256>>>(stats + 512, g2, beta2, scale + 256, shift + 256);

    bn_relu_tr_kernel<<<dim3(NPTS / 32, CO / 32, BATCH), dim3(32, 32)>>>(
        y2, scale + 256, shift + 256, out);
}

// round 6
// speedup vs baseline: 2.4683x; 1.2896x over previous
#include <cuda_runtime.h>
#include <cuda_bf16.h>
#include <cstdint>

// Problem constants
#define BATCH 16
#define NPTS  4096
#define MPTS  1024
#define C1    256
#define C2    512
#define CO    256
#define RTOT  65536
#define NZ    4
#define CHM   (MPTS / NZ)   // 256

// ---------------- scratch (static __device__ globals; no allocation) ----------
__device__ float  g_y  [(size_t)RTOT * CO];
__device__ float  g_y2 [(size_t)RTOT * CO];
__device__ float  g_Z  [(size_t)BATCH * MPTS * CO];     // P2 * W1a^T
__device__ unsigned short g_Bhi1a[CO * 512];
__device__ unsigned short g_Blo1a[CO * 512];
__device__ unsigned short g_Bhi1b[CO * 256];
__device__ unsigned short g_Blo1b[CO * 256];
__device__ unsigned short g_Bhi2 [CO * 256];
__device__ unsigned short g_Blo2 [CO * 256];
__device__ float  g_pd [(size_t)NZ * RTOT * 3];
__device__ int    g_pi [(size_t)NZ * RTOT * 3];
__device__ int    g_idx3[RTOT * 3];
__device__ double g_stats[1024];
__device__ float  g_scale[512];
__device__ float  g_shift[512];

// ---------------- helpers ---------------------------------------------------------
__device__ __forceinline__ uint32_t smem_u32(const void* p) {
    uint32_t a;
    asm("{ .reg .u64 t; cvta.to.shared.u64 t, %1; cvt.u32.u64 %0, t; }" : "=r"(a) : "l"(p));
    return a;
}

__device__ __forceinline__ void cpa16(uint32_t s, const void* g) {
    asm volatile("cp.async.ca.shared.global [%0], [%1], 16;" :: "r"(s), "l"(g));
}
#define CP_COMMIT() asm volatile("cp.async.commit_group;" ::: "memory")
#define CP_WAIT0()  asm volatile("cp.async.wait_group 0;" ::: "memory")

#define LDSM4(r, addr) \
    asm volatile("ldmatrix.sync.aligned.m8n8.x4.shared.b16 {%0,%1,%2,%3}, [%4];" \
                 : "=r"((r)[0]), "=r"((r)[1]), "=r"((r)[2]), "=r"((r)[3]) : "r"(addr))

#define MMA16816(d, a, b0, b1) \
    asm volatile("mma.sync.aligned.m16n8k16.row.col.f32.bf16.bf16.f32 " \
                 "{%0,%1,%2,%3}, {%4,%5,%6,%7}, {%8,%9}, {%0,%1,%2,%3};" \
                 : "+f"((d)[0]), "+f"((d)[1]), "+f"((d)[2]), "+f"((d)[3]) \
                 : "r"((a)[0]), "r"((a)[1]), "r"((a)[2]), "r"((a)[3]), "r"(b0), "r"(b1))

__device__ __forceinline__ void split4(float4 v, uint2& hi, uint2& lo) {
    __nv_bfloat16 h0 = __float2bfloat16_rn(v.x);
    __nv_bfloat16 h1 = __float2bfloat16_rn(v.y);
    __nv_bfloat16 h2 = __float2bfloat16_rn(v.z);
    __nv_bfloat16 h3 = __float2bfloat16_rn(v.w);
    __nv_bfloat16 l0 = __float2bfloat16_rn(v.x - __bfloat162float(h0));
    __nv_bfloat16 l1 = __float2bfloat16_rn(v.y - __bfloat162float(h1));
    __nv_bfloat16 l2 = __float2bfloat16_rn(v.z - __bfloat162float(h2));
    __nv_bfloat16 l3 = __float2bfloat16_rn(v.w - __bfloat162float(h3));
    hi.x = (uint32_t)__bfloat16_as_ushort(h0) | ((uint32_t)__bfloat16_as_ushort(h1) << 16);
    hi.y = (uint32_t)__bfloat16_as_ushort(h2) | ((uint32_t)__bfloat16_as_ushort(h3) << 16);
    lo.x = (uint32_t)__bfloat16_as_ushort(l0) | ((uint32_t)__bfloat16_as_ushort(l1) << 16);
    lo.y = (uint32_t)__bfloat16_as_ushort(l2) | ((uint32_t)__bfloat16_as_ushort(l3) << 16);
}

// ---------------- small utility kernels -----------------------------------------
__global__ void zero_stats_kernel(double* stats) { stats[threadIdx.x] = 0.0; }

// W1 (256 x 768) -> W1a split (256 x 512) + W1b split (256 x 256)
__global__ void prep_w1_kernel(const float* __restrict__ W,
                               unsigned short* __restrict__ BhiA, unsigned short* __restrict__ BloA,
                               unsigned short* __restrict__ BhiB, unsigned short* __restrict__ BloB) {
    int idx = blockIdx.x * 256 + threadIdx.x;      // 256*768
    int n = idx / 768, k = idx % 768;
    float v = W[idx];
    __nv_bfloat16 hi = __float2bfloat16_rn(v);
    __nv_bfloat16 lo = __float2bfloat16_rn(v - __bfloat162float(hi));
    if (k < 512) {
        BhiA[n * 512 + k] = __bfloat16_as_ushort(hi);
        BloA[n * 512 + k] = __bfloat16_as_ushort(lo);
    } else {
        BhiB[n * 256 + (k - 512)] = __bfloat16_as_ushort(hi);
        BloB[n * 256 + (k - 512)] = __bfloat16_as_ushort(lo);
    }
}

__global__ void prep_w2_kernel(const float* __restrict__ W,
                               unsigned short* __restrict__ Bhi,
                               unsigned short* __restrict__ Blo) {
    int idx = blockIdx.x * 256 + threadIdx.x;
    float v = W[idx];
    __nv_bfloat16 hi = __float2bfloat16_rn(v);
    __nv_bfloat16 lo = __float2bfloat16_rn(v - __bfloat162float(hi));
    Bhi[idx] = __bfloat16_as_ushort(hi);
    Blo[idx] = __bfloat16_as_ushort(lo);
}

// ---------------- 3-NN: partial over MPTS chunks, then merge ---------------------
__global__ void three_nn_part_kernel(const float* __restrict__ xyz1,
                                     const float* __restrict__ xyz2,
                                     float* __restrict__ pd, int* __restrict__ pi) {
    __shared__ float sx[CHM], sy[CHM], sz[CHM], s2[CHM];
    int b = blockIdx.y, ch = blockIdx.z;
    int tid = threadIdx.x;
    const float* p2 = xyz2 + ((size_t)b * MPTS + ch * CHM) * 3;
    {
        float px = p2[tid * 3 + 0], py = p2[tid * 3 + 1], pz = p2[tid * 3 + 2];
        sx[tid] = px; sy[tid] = py; sz[tid] = pz;
        s2[tid] = px * px + py * py + pz * pz;
    }
    __syncthreads();

    int n = blockIdx.x * 256 + tid;
    size_t r = (size_t)b * NPTS + n;
    float x = xyz1[r * 3 + 0], y = xyz1[r * 3 + 1], z = xyz1[r * 3 + 2];

    // d' = |p|^2 - 2 (q . p)  (true sq-dist minus per-query constant; ordering preserved)
    float d0 = 1e30f, d1 = 1e30f, d2v = 1e30f;
    int   i0 = 0, i1 = 0, i2 = 0;
    #pragma unroll 4
    for (int j = 0; j < CHM; j++) {
        float dot = fmaf(x, sx[j], fmaf(y, sy[j], z * sz[j]));
        float d = fmaf(-2.f, dot, s2[j]);
        if (d < d0)        { d2v = d1; i2 = i1; d1 = d0; i1 = i0; d0 = d; i0 = j; }
        else if (d < d1)   { d2v = d1; i2 = i1; d1 = d;  i1 = j; }
        else if (d < d2v)  { d2v = d;  i2 = j; }
    }
    size_t o = ((size_t)ch * RTOT + r) * 3;
    pd[o + 0] = d0;  pd[o + 1] = d1;  pd[o + 2] = d2v;
    pi[o + 0] = ch * CHM + i0;
    pi[o + 1] = ch * CHM + i1;
    pi[o + 2] = ch * CHM + i2;
}

__global__ void three_nn_merge_kernel(const float* __restrict__ pd,
                                      const int* __restrict__ pi,
                                      int* __restrict__ idx) {
    size_t r = (size_t)blockIdx.x * 256 + threadIdx.x;
    float d0 = 1e30f, d1 = 1e30f, d2v = 1e30f;
    int   i0 = 0, i1 = 0, i2 = 0;
    #pragma unroll
    for (int ch = 0; ch < NZ; ch++) {
        size_t o = ((size_t)ch * RTOT + r) * 3;
        #pragma unroll
        for (int k = 0; k < 3; k++) {
            float d = pd[o + k];
            int   ii = pi[o + k];
            if (d < d0)        { d2v = d1; i2 = i1; d1 = d0; i1 = i0; d0 = d; i0 = ii; }
            else if (d < d1)   { d2v = d1; i2 = i1; d1 = d;  i1 = ii; }
            else if (d < d2v)  { d2v = d;  i2 = ii; }
        }
    }
    idx[r * 3 + 0] = i0;
    idx[r * 3 + 1] = i1;
    idx[r * 3 + 2] = i2;
}

// ---------------- split-bf16 HMMA GEMM (plain / BN converter, gather/stats epi) --
// Y(M x 256) = A(M x K) * B(256 x K)^T [+ gather3(Z)/3] ; CTA 128M x 256N, 8 warps.
#define RS    40
#define RSRAW 36

#define SZ_ABUF 10240                 // 128*RS*2
#define SZ_BBUF 20480                 // 256*RS*2
#define OFF_A    0                    // Ahi[2], Alo[2]
#define OFF_B    40960                // Bhi[2], Blo[2]
#define OFF_RAW  122880               // 18432
#define OFF_IDX  141312               // 1536
#define OFF_SC   142848               // 1024
#define OFF_SH   143872               // 1024
#define OFF_SUM  144896               // 1024
#define OFF_SQ   145920               // 1024
#define SM_TOTAL 146944

template<int K, int BN, int GATHER, int STATS>
__global__ void __launch_bounds__(256, 1)
gemm_kernel(const float* __restrict__ Aptr,
            const unsigned short* __restrict__ Bhi,
            const unsigned short* __restrict__ Blo,
            const int* __restrict__ idx3,
            const float* __restrict__ Z,
            const float* __restrict__ scale,
            const float* __restrict__ shift,
            float* __restrict__ Y,
            double* __restrict__ stats) {
    constexpr int KCH = K / 32;
    extern __shared__ char sm[];
    uint32_t sb = smem_u32(sm);

    int tid = threadIdx.x, lane = tid & 31, wid = tid >> 5;
    int wm = wid & 1, wn = wid >> 1;
    int rbase = blockIdx.x * 128;

    if (GATHER) {
        for (int i = tid; i < 384; i += 256)
            ((int*)(sm + OFF_IDX))[i] = idx3[(size_t)rbase * 3 + i];
    }
    if (BN) {
        ((float*)(sm + OFF_SC))[tid] = scale[tid];
        ((float*)(sm + OFF_SH))[tid] = shift[tid];
    }
    if (STATS) {
        ((float*)(sm + OFF_SUM))[tid] = 0.f;
        ((float*)(sm + OFF_SQ))[tid]  = 0.f;
    }
    __syncthreads();

    auto cp_chunk = [&](int c, int s) {
        int k0 = c * 32;
        #pragma unroll
        for (int it = 0; it < 4; it++) {       // B: 1024 16B slots per matrix
            int slot = it * 256 + tid;
            int row = slot >> 2, q = slot & 3;
            uint32_t d = sb + OFF_B + s * SZ_BBUF + (uint32_t)(row * RS + q * 8) * 2;
            cpa16(d,               Bhi + (size_t)row * K + k0 + q * 8);
            cpa16(d + 2 * SZ_BBUF, Blo + (size_t)row * K + k0 + q * 8);
        }
        #pragma unroll
        for (int it = 0; it < 4; it++) {       // A raw: 1024 16B slots
            int slot = it * 256 + tid;
            int row = slot >> 3, q = slot & 7;
            uint32_t d = sb + OFF_RAW + (uint32_t)(row * RSRAW + q * 4) * 4;
            cpa16(d, Aptr + (size_t)(rbase + row) * K + k0 + q * 4);
        }
        CP_COMMIT();
    };

    auto convert_chunk = [&](int c, int s) {
        int k0 = c * 32;
        #pragma unroll
        for (int it = 0; it < 4; it++) {
            int slot = it * 256 + tid;
            int row = slot >> 3, q = slot & 7;
            float4 v = *(const float4*)(sm + OFF_RAW + (uint32_t)(row * RSRAW + q * 4) * 4);
            if (BN) {
                const float* sc = (const float*)(sm + OFF_SC) + k0 + q * 4;
                const float* sh = (const float*)(sm + OFF_SH) + k0 + q * 4;
                v.x = fmaxf(v.x * sc[0] + sh[0], 0.f);
                v.y = fmaxf(v.y * sc[1] + sh[1], 0.f);
                v.z = fmaxf(v.z * sc[2] + sh[2], 0.f);
                v.w = fmaxf(v.w * sc[3] + sh[3], 0.f);
            }
            uint2 hi, lo;
            split4(v, hi, lo);
            uint32_t aoff = (uint32_t)(row * RS + q * 4) * 2;
            *(uint2*)(sm + OFF_A + s * SZ_ABUF + aoff) = hi;
            *(uint2*)(sm + OFF_A + 2 * SZ_ABUF + s * SZ_ABUF + aoff) = lo;
        }
    };

    cp_chunk(0, 0);
    CP_WAIT0();
    convert_chunk(0, 0);
    __syncthreads();

    float acc[4][8][4] = {};

    for (int c = 0; c < KCH; c++) {
        int s = c & 1;
        if (c + 1 < KCH) cp_chunk(c + 1, 1 - s);

        uint32_t sAhi = sb + OFF_A + s * SZ_ABUF;
        uint32_t sAlo = sAhi + 2 * SZ_ABUF;
        uint32_t sBhi = sb + OFF_B + s * SZ_BBUF;
        uint32_t sBlo = sBhi + 2 * SZ_BBUF;

        #pragma unroll
        for (int ks = 0; ks < 2; ks++) {
            int arow = wm * 64 + (lane & 15);
            int akoff = ks * 16 + (lane >> 4) * 8;
            int brow = wn * 64 + (lane & 7) + ((lane >> 4) & 1) * 8;
            int bkoff = ks * 16 + ((lane >> 3) & 1) * 8;

            uint32_t ah[4][4], al[4][4], bh[4][4];
            #pragma unroll
            for (int mi = 0; mi < 4; mi++) {
                LDSM4(ah[mi], sAhi + (uint32_t)((arow + mi * 16) * RS + akoff) * 2);
                LDSM4(al[mi], sAlo + (uint32_t)((arow + mi * 16) * RS + akoff) * 2);
            }
            #pragma unroll
            for (int jj = 0; jj < 4; jj++)
                LDSM4(bh[jj], sBhi + (uint32_t)((brow + jj * 16) * RS + bkoff) * 2);

            #pragma unroll
            for (int mi = 0; mi < 4; mi++)
                #pragma unroll
                for (int jj = 0; jj < 4; jj++) {
                    MMA16816(acc[mi][jj * 2 + 0], ah[mi], bh[jj][0], bh[jj][1]);
                    MMA16816(acc[mi][jj * 2 + 1], ah[mi], bh[jj][2], bh[jj][3]);
                }
            #pragma unroll
            for (int mi = 0; mi < 4; mi++)
                #pragma unroll
                for (int jj = 0; jj < 4; jj++) {
                    MMA16816(acc[mi][jj * 2 + 0], al[mi], bh[jj][0], bh[jj][1]);
                    MMA16816(acc[mi][jj * 2 + 1], al[mi], bh[jj][2], bh[jj][3]);
                }
            uint32_t bl[4][4];
            #pragma unroll
            for (int jj = 0; jj < 4; jj++)
                LDSM4(bl[jj], sBlo + (uint32_t)((brow + jj * 16) * RS + bkoff) * 2);
            #pragma unroll
            for (int mi = 0; mi < 4; mi++)
                #pragma unroll
                for (int jj = 0; jj < 4; jj++) {
                    MMA16816(acc[mi][jj * 2 + 0], ah[mi], bl[jj][0], bl[jj][1]);
                    MMA16816(acc[mi][jj * 2 + 1], ah[mi], bl[jj][2], bl[jj][3]);
                }
        }
        if (c + 1 < KCH) {
            CP_WAIT0();
            convert_chunk(c + 1, 1 - s);
        }
        __syncthreads();
    }

    // ---- epilogue ----
    if (GATHER) {
        int b = rbase >> 12;
        const float* Zb = Z + (size_t)b * MPTS * CO;
        const float third = 1.0f / 3.0f;
        const int* idxsm = (const int*)(sm + OFF_IDX);
        #pragma unroll
        for (int mi = 0; mi < 4; mi++) {
            #pragma unroll
            for (int r2 = 0; r2 < 2; r2++) {
                int lrow = wm * 64 + (lane >> 2) + mi * 16 + r2 * 8;
                const int* si = idxsm + lrow * 3;
                const float* z0 = Zb + (size_t)si[0] * CO;
                const float* z1 = Zb + (size_t)si[1] * CO;
                const float* z2 = Zb + (size_t)si[2] * CO;
                #pragma unroll
                for (int nb = 0; nb < 8; nb++) {
                    int col = wn * 64 + nb * 8 + (lane & 3) * 2;
                    float2 a0 = *(const float2*)(z0 + col);
                    float2 a1 = *(const float2*)(z1 + col);
                    float2 a2 = *(const float2*)(z2 + col);
                    acc[mi][nb][r2 * 2 + 0] += (a0.x + a1.x + a2.x) * third;
                    acc[mi][nb][r2 * 2 + 1] += (a0.y + a1.y + a2.y) * third;
                }
            }
        }
    }

    int rr = rbase + wm * 64 + (lane >> 2);
    int cc0 = wn * 64 + (lane & 3) * 2;
    #pragma unroll
    for (int mi = 0; mi < 4; mi++) {
        #pragma unroll
        for (int nb = 0; nb < 8; nb++) {
            int col = cc0 + nb * 8;
            float* a = acc[mi][nb];
            *(float2*)(Y + (size_t)(rr + mi * 16)     * CO + col) = make_float2(a[0], a[1]);
            *(float2*)(Y + (size_t)(rr + mi * 16 + 8) * CO + col) = make_float2(a[2], a[3]);
        }
    }
    if (STATS) {
        float* ssum = (float*)(sm + OFF_SUM);
        float* ssq  = (float*)(sm + OFF_SQ);
        #pragma unroll
        for (int nb = 0; nb < 8; nb++) {
            int col = cc0 + nb * 8;
            float s0 = 0.f, s1 = 0.f, q0 = 0.f, q1 = 0.f;
            #pragma unroll
            for (int mi = 0; mi < 4; mi++) {
                float* a = acc[mi][nb];
                s0 += a[0] + a[2];
                s1 += a[1] + a[3];
                q0 += a[0] * a[0] + a[2] * a[2];
                q1 += a[1] * a[1] + a[3] * a[3];
            }
            atomicAdd(&ssum[col], s0);
            atomicAdd(&ssq[col],  q0);
            atomicAdd(&ssum[col + 1], s1);
            atomicAdd(&ssq[col + 1],  q1);
        }
        __syncthreads();
        atomicAdd(&stats[tid],      (double)ssum[tid]);
        atomicAdd(&stats[CO + tid], (double)ssq[tid]);
    }
}

// ---------------- finalize BN params ----------------------------------------------
__global__ void finalize_kernel(const double* __restrict__ sums,
                                const float* __restrict__ g, const float* __restrict__ beta,
                                float* __restrict__ scale, float* __restrict__ shift) {
    int c = threadIdx.x;
    double mean = sums[c] * (1.0 / RTOT);
    double var = sums[CO + c] * (1.0 / RTOT) - mean * mean;
    float sc = g[c] * rsqrtf((float)var + 1e-5f);
    scale[c] = sc;
    shift[c] = beta[c] - (float)mean * sc;
}

// ---------------- final BN + ReLU + transpose to (b, c, n) -------------------------
__global__ void bn_relu_tr_kernel(const float* __restrict__ y,
                                  const float* __restrict__ scale, const float* __restrict__ shift,
                                  float* __restrict__ out) {
    __shared__ float t[32][33];
    int b = blockIdx.z;
    int n0 = blockIdx.x * 32, c0 = blockIdx.y * 32;
    int n = n0 + threadIdx.y, c = c0 + threadIdx.x;
    float v = y[((size_t)b * NPTS + n) * CO + c];
    v = fmaxf(v * scale[c] + shift[c], 0.f);
    t[threadIdx.y][threadIdx.x] = v;
    __syncthreads();
    out[((size_t)b * CO + c0 + threadIdx.y) * NPTS + n0 + threadIdx.x] = t[threadIdx.x][threadIdx.y];
}

// ---------------- launch -----------------------------------------------------------
extern "C" void kernel_launch(void* const* d_in, const int* in_sizes, int n_in,
                              void* d_out, int out_size) {
    const float* xyz1    = (const float*)d_in[0];
    const float* xyz2    = (const float*)d_in[1];
    const float* points1 = (const float*)d_in[2];
    const float* points2 = (const float*)d_in[3];
    const float* W1      = (const float*)d_in[4];
    const float* g1      = (const float*)d_in[6];
    const float* beta1   = (const float*)d_in[7];
    const float* W2      = (const float*)d_in[8];
    const float* g2      = (const float*)d_in[10];
    const float* beta2   = (const float*)d_in[11];
    float* out = (float*)d_out;

    float *y, *y2, *Z, *pd, *scale, *shift;
    unsigned short *Bhi1a, *Blo1a, *Bhi1b, *Blo1b, *Bhi2, *Blo2;
    int *pi, *idx3;
    double* stats;
    cudaGetSymbolAddress((void**)&y, g_y);
    cudaGetSymbolAddress((void**)&y2, g_y2);
    cudaGetSymbolAddress((void**)&Z, g_Z);
    cudaGetSymbolAddress((void**)&Bhi1a, g_Bhi1a);
    cudaGetSymbolAddress((void**)&Blo1a, g_Blo1a);
    cudaGetSymbolAddress((void**)&Bhi1b, g_Bhi1b);
    cudaGetSymbolAddress((void**)&Blo1b, g_Blo1b);
    cudaGetSymbolAddress((void**)&Bhi2, g_Bhi2);
    cudaGetSymbolAddress((void**)&Blo2, g_Blo2);
    cudaGetSymbolAddress((void**)&pd, g_pd);
    cudaGetSymbolAddress((void**)&pi, g_pi);
    cudaGetSymbolAddress((void**)&idx3, g_idx3);
    cudaGetSymbolAddress((void**)&stats, g_stats);
    cudaGetSymbolAddress((void**)&scale, g_scale);
    cudaGetSymbolAddress((void**)&shift, g_shift);

    cudaFuncSetAttribute(gemm_kernel<512,0,0,0>, cudaFuncAttributeMaxDynamicSharedMemorySize, SM_TOTAL);
    cudaFuncSetAttribute(gemm_kernel<256,0,1,1>, cudaFuncAttributeMaxDynamicSharedMemorySize, SM_TOTAL);
    cudaFuncSetAttribute(gemm_kernel<256,1,0,1>, cudaFuncAttributeMaxDynamicSharedMemorySize, SM_TOTAL);

    zero_stats_kernel<<<1, 1024>>>(stats);
    prep_w1_kernel<<<(CO * 768) / 256, 256>>>(W1, Bhi1a, Blo1a, Bhi1b, Blo1b);
    prep_w2_kernel<<<(CO * 256) / 256, 256>>>(W2, Bhi2, Blo2);

    three_nn_part_kernel<<<dim3(NPTS / 256, BATCH, NZ), 256>>>(xyz1, xyz2, pd, pi);
    three_nn_merge_kernel<<<RTOT / 256, 256>>>(pd, pi, idx3);

    // Z = points2 * W1a^T   (M = 16*1024, K = 512)
    gemm_kernel<512,0,0,0><<<(BATCH * MPTS) / 128, 256, SM_TOTAL>>>(
        points2, Bhi1a, Blo1a, nullptr, nullptr, nullptr, nullptr, Z, nullptr);

    // Y1 = points1 * W1b^T + gather3(Z)/3 ; stats
    gemm_kernel<256,0,1,1><<<RTOT / 128, 256, SM_TOTAL>>>(
        points1, Bhi1b, Blo1b, idx3, Z, nullptr, nullptr, y, stats);
    finalize_kernel<<<1, 256>>>(stats, g1, beta1, scale, shift);

    // Y2 = relu(bn(Y1)) * W2^T ; stats
    gemm_kernel<256,1,0,1><<<RTOT / 128, 256, SM_TOTAL>>>(
        y, Bhi2, Blo2, nullptr, nullptr, scale, shift, y2, stats + 512);
    finalize_kernel<<<1, 256>>>(stats + 512, g2, beta2, scale + 256, shift + 256);

    bn_relu_tr_kernel<<<dim3(NPTS / 32, CO / 32, BATCH), dim3(32, 32)>>>(
        y2, scale + 256, shift + 256, out);
}